// round 10
// baseline (speedup 1.0000x reference)
#include <cuda_runtime.h>
#include <math.h>
#include <stddef.h>
#include <stdint.h>

// Problem constants
#define B_  2
#define S_  2048
#define D_  1024
#define H_  16
#define FK_ 32
#define DK_ 64
#define BH_ (B_*H_)

// ---------------- scratch (__device__ globals; no allocation allowed) ----------------
__device__ float g_LT[H_*FK_*DK_];        // LT[h][j][c] = (Wa@Wb@Wa2)[c][j]
__device__ float g_vp[B_*S_*D_];          // v@Wv+bv
__device__ float g_concat[B_*S_*D_];      // attention output pre-Wo
__device__ float g_X[BH_*S_*FK_];         // X[bh][s][32] = q.L
__device__ float g_Y[BH_*S_*FK_];         // Y[bh][t][32] = q.R^T

// ---------------- 1) collapse Wa@Wb@Wa2 per head (fp32; entries ~5e2, err ~1e-3) ----
__global__ void compute_L_kernel(const float* __restrict__ W_A,
                                 const float* __restrict__ W_A2) {
    int h = blockIdx.x;
    __shared__ float T1[64*64];
    const float* WAh  = W_A  + h*2048;
    const float* WA2h = W_A2 + h*2048;

    for (int idx = threadIdx.x; idx < 4096; idx += blockDim.x) {
        int c = idx >> 6, d = idx & 63;
        float acc = 0.f;
        #pragma unroll 8
        for (int j = 0; j < 32; j++)
            acc = fmaf(WAh[c*32 + j], WAh[j*64 + d], acc);
        T1[idx] = acc;
    }
    __syncthreads();
    for (int idx = threadIdx.x; idx < 2048; idx += blockDim.x) {
        int c = idx >> 5, j = idx & 31;
        float acc = 0.f;
        #pragma unroll 8
        for (int d = 0; d < 64; d++)
            acc = fmaf(T1[c*64 + d], WA2h[d*32 + j], acc);
        g_LT[h*2048 + j*64 + c] = acc;    // transposed for coalesced xy reads
    }
}

// ---------------- 2) X = q.L, Y = q.R^T per head (rank-32 factors) ----------------
__global__ __launch_bounds__(512)
void xy_kernel(const float* __restrict__ q, const float* __restrict__ W_A2) {
    int token = blockIdx.x;                  // b*2048+s
    int b = token >> 11, s = token & 2047;
    __shared__ float qs[D_];
    const float* qrow = q + (size_t)token * D_;
    for (int i = threadIdx.x; i < D_; i += 512) qs[i] = qrow[i];
    __syncthreads();
    int j = threadIdx.x & 31;
    int h = threadIdx.x >> 5;               // 0..15
    const float* qh = qs + h*64;
    const float* LTh = g_LT + h*2048 + j*64;  // contiguous 64 floats
    float x = 0.f;
    #pragma unroll 8
    for (int c = 0; c < 64; c++) x = fmaf(qh[c], LTh[c], x);
    const float* Rh = W_A2 + h*2048 + j*64;   // Wb2[h][j][d]
    float y = 0.f;
    #pragma unroll 8
    for (int d = 0; d < 64; d++) y = fmaf(qh[d], Rh[d], y);
    size_t o = (((size_t)(b*16 + h))*2048 + s)*32 + j;
    g_X[o] = x;
    g_Y[o] = y;
}

// ---------------- 3) scalar SGEMM (measured ~39.6 TF/s, at SIMT fp32 ceiling) ------
__global__ __launch_bounds__(256)
void sgemm_nn_bias(int M, int N, int K,
                   const float* __restrict__ A,
                   const float* __restrict__ Bm,
                   const float* __restrict__ bias,
                   float* __restrict__ C) {
    __shared__ float As[16][128];
    __shared__ float Bs[16][128];
    int bm = blockIdx.y * 128;
    int bn = blockIdx.x * 128;
    int tid = threadIdx.x;
    int tx = tid & 15, ty = tid >> 4;

    float acc[8][8];
    #pragma unroll
    for (int i = 0; i < 8; i++)
        #pragma unroll
        for (int j = 0; j < 8; j++) acc[i][j] = 0.f;

    int arow = tid >> 1;
    int acol = (tid & 1) * 8;
    int brow = tid >> 4;
    int bcol = (tid & 15) * 8;

    for (int k0 = 0; k0 < K; k0 += 16) {
        const float* Ap = A + (size_t)(bm + arow) * K + k0 + acol;
        float4 a0 = *(const float4*)Ap;
        float4 a1 = *(const float4*)(Ap + 4);
        As[acol+0][arow] = a0.x; As[acol+1][arow] = a0.y;
        As[acol+2][arow] = a0.z; As[acol+3][arow] = a0.w;
        As[acol+4][arow] = a1.x; As[acol+5][arow] = a1.y;
        As[acol+6][arow] = a1.z; As[acol+7][arow] = a1.w;

        const float* Bp = Bm + (size_t)(k0 + brow) * N + bn + bcol;
        *(float4*)&Bs[brow][bcol]     = *(const float4*)Bp;
        *(float4*)&Bs[brow][bcol + 4] = *(const float4*)(Bp + 4);
        __syncthreads();

        #pragma unroll
        for (int kk = 0; kk < 16; kk++) {
            float a[8], b[8];
            *(float4*)(a)     = *(float4*)&As[kk][ty*8];
            *(float4*)(a + 4) = *(float4*)&As[kk][ty*8 + 4];
            *(float4*)(b)     = *(float4*)&Bs[kk][tx*8];
            *(float4*)(b + 4) = *(float4*)&Bs[kk][tx*8 + 4];
            #pragma unroll
            for (int i = 0; i < 8; i++)
                #pragma unroll
                for (int j = 0; j < 8; j++)
                    acc[i][j] = fmaf(a[i], b[j], acc[i][j]);
        }
        __syncthreads();
    }

    #pragma unroll
    for (int i = 0; i < 8; i++) {
        int row = bm + ty*8 + i;
        float* Cp = C + (size_t)row * N + bn + tx*8;
        float o[8];
        #pragma unroll
        for (int j = 0; j < 8; j++)
            o[j] = acc[i][j] + bias[bn + tx*8 + j];
        *(float4*)(Cp)     = *(float4*)(o);
        *(float4*)(Cp + 4) = *(float4*)(o + 4);
    }
}

// ---------------- 4) FUSED: scores (X.Y^T) + online softmax + sparse PV ------------
// 64-row stripes for occupancy: smem 58KB (As 8K + Bs 16K + SC 64x132 pad), acc 4x8,
// scan 4 thr/row x 16 dims, __launch_bounds__(256,3) -> 3 CTA/SM (24 warps, 37.5%).
// Semantics identical to R9 (exact fp32 scores, online softmax, exp==0 skip).
#define SCS 132
#define SM_B  8192
#define SM_SC 24576
#define SMEM_FUSED (24576 + 64*SCS*4)   // 58368 bytes

__global__ __launch_bounds__(256, 3)
void fused_attn_kernel() {
    extern __shared__ __align__(128) char sm[];
    float* As = (float*)(sm);             // [32][64]   As[k][row]
    float* Bs = (float*)(sm + SM_B);      // [32][128]  Bs[k][col]
    float* SC = (float*)(sm + SM_SC);     // [64][SCS]

    int tid = threadIdx.x;
    int stile = blockIdx.x, bh = blockIdx.y;
    int b = bh >> 4, h = bh & 15;
    int s0 = stile * 64;
    int tx = tid & 15, ty = tid >> 4;

    const float* X = g_X + ((size_t)bh*2048 + s0)*32;
    const float* Y = g_Y + (size_t)bh*2048*32;

    // ---- stage A (transposed) once: thread -> row tid>>2, quad tid&3 ----
    {
        int arow = tid >> 2, aq = tid & 3;
        const float4* xr = (const float4*)(X + arow*32 + aq*8);
        float4 v0 = xr[0], v1 = xr[1];
        int k0 = aq*8;
        As[(k0+0)*64+arow]=v0.x; As[(k0+1)*64+arow]=v0.y;
        As[(k0+2)*64+arow]=v0.z; As[(k0+3)*64+arow]=v0.w;
        As[(k0+4)*64+arow]=v1.x; As[(k0+5)*64+arow]=v1.y;
        As[(k0+6)*64+arow]=v1.z; As[(k0+7)*64+arow]=v1.w;
    }

    // ---- scan/PV state: row rt = tid>>2 (0..63), dim chunk sub = tid&3 (16 dims) --
    int rt = tid >> 2, sub = tid & 3;
    const float* vbase = g_vp + (size_t)b*2048*D_ + h*64 + sub*16;
    float m   = __int_as_float(0xff800000);   // -inf
    float den = 0.f;
    float4 o4[4];
    #pragma unroll
    for (int jj = 0; jj < 4; jj++) o4[jj] = make_float4(0.f, 0.f, 0.f, 0.f);

    int brow = tid >> 1, bhalf = tid & 1;

    for (int tt = 0; tt < 16; tt++) {
        int t0 = tt * 128;
        // stage B tile (transposed): thread -> col tid>>1 (0..127), half tid&1
        {
            const float4* yr = (const float4*)(Y + (size_t)(t0 + brow)*32 + bhalf*16);
            float4 v0 = yr[0], v1 = yr[1], v2 = yr[2], v3 = yr[3];
            int k0 = bhalf*16;
            Bs[(k0+ 0)*128+brow]=v0.x; Bs[(k0+ 1)*128+brow]=v0.y;
            Bs[(k0+ 2)*128+brow]=v0.z; Bs[(k0+ 3)*128+brow]=v0.w;
            Bs[(k0+ 4)*128+brow]=v1.x; Bs[(k0+ 5)*128+brow]=v1.y;
            Bs[(k0+ 6)*128+brow]=v1.z; Bs[(k0+ 7)*128+brow]=v1.w;
            Bs[(k0+ 8)*128+brow]=v2.x; Bs[(k0+ 9)*128+brow]=v2.y;
            Bs[(k0+10)*128+brow]=v2.z; Bs[(k0+11)*128+brow]=v2.w;
            Bs[(k0+12)*128+brow]=v3.x; Bs[(k0+13)*128+brow]=v3.y;
            Bs[(k0+14)*128+brow]=v3.z; Bs[(k0+15)*128+brow]=v3.w;
        }
        __syncthreads();

        // ---- 64x128 GEMM tile, 4x8 microtile ----
        float acc[4][8];
        #pragma unroll
        for (int i = 0; i < 4; i++)
            #pragma unroll
            for (int j = 0; j < 8; j++) acc[i][j] = 0.f;

        #pragma unroll
        for (int kk = 0; kk < 32; kk++) {
            float a[4], bb[8];
            *(float4*)(a)      = *(float4*)&As[kk*64 + ty*4];
            *(float4*)(bb)     = *(float4*)&Bs[kk*128 + tx*8];
            *(float4*)(bb + 4) = *(float4*)&Bs[kk*128 + tx*8 + 4];
            #pragma unroll
            for (int i = 0; i < 4; i++)
                #pragma unroll
                for (int j = 0; j < 8; j++)
                    acc[i][j] = fmaf(a[i], bb[j], acc[i][j]);
        }

        // spill acc -> SC (padded stride)
        #pragma unroll
        for (int i = 0; i < 4; i++) {
            *(float4*)&SC[(ty*4+i)*SCS + tx*8]     = *(float4*)&acc[i][0];
            *(float4*)&SC[(ty*4+i)*SCS + tx*8 + 4] = *(float4*)&acc[i][4];
        }
        __syncthreads();

        // ---- scan full row (4 threads/row, broadcast LDS), online softmax + PV ----
        const float* rp = SC + rt*SCS;
        #pragma unroll 4
        for (int j4 = 0; j4 < 32; j4++) {
            float4 x4 = *(const float4*)(rp + j4*4);
            float xs[4] = {x4.x, x4.y, x4.z, x4.w};
            #pragma unroll
            for (int u = 0; u < 4; u++) {
                float x = xs[u];
                int t = t0 + j4*4 + u;
                if (x > m) {
                    float r = __expf(m - x);
                    den = den * r + 1.f;
                    const float4* vr = (const float4*)(vbase + (size_t)t * D_);
                    #pragma unroll
                    for (int jj = 0; jj < 4; jj++) {
                        float4 v = vr[jj];
                        o4[jj].x = fmaf(o4[jj].x, r, v.x);
                        o4[jj].y = fmaf(o4[jj].y, r, v.y);
                        o4[jj].z = fmaf(o4[jj].z, r, v.z);
                        o4[jj].w = fmaf(o4[jj].w, r, v.w);
                    }
                    m = x;
                } else {
                    float dx = x - m;
                    if (dx > -95.0f) {      // exp underflows to exact 0 below this
                        float w = __expf(dx);
                        den += w;
                        const float4* vr = (const float4*)(vbase + (size_t)t * D_);
                        #pragma unroll
                        for (int jj = 0; jj < 4; jj++) {
                            float4 v = vr[jj];
                            o4[jj].x = fmaf(w, v.x, o4[jj].x);
                            o4[jj].y = fmaf(w, v.y, o4[jj].y);
                            o4[jj].z = fmaf(w, v.z, o4[jj].z);
                            o4[jj].w = fmaf(w, v.w, o4[jj].w);
                        }
                    }
                }
            }
        }
        __syncthreads();   // scan done before next spill / B restage
    }

    // ---- write out: o/den -> concat[b, s0+rt, h*64 + sub*16 ..] ----
    float inv = 1.f / den;
    float* op = g_concat + ((size_t)(b*2048 + s0 + rt))*D_ + h*64 + sub*16;
    #pragma unroll
    for (int jj = 0; jj < 4; jj++) {
        float4 r = o4[jj];
        r.x *= inv; r.y *= inv; r.z *= inv; r.w *= inv;
        *(float4*)(op + jj*4) = r;
    }
}

// ---------------- launcher ----------------
extern "C" void kernel_launch(void* const* d_in, const int* in_sizes, int n_in,
                              void* d_out, int out_size) {
    const float* q    = (const float*)d_in[0];
    // d_in[1] = k (unused in reference forward)
    const float* v    = (const float*)d_in[2];
    const float* Wv   = (const float*)d_in[3];
    const float* bv   = (const float*)d_in[4];
    const float* W_A  = (const float*)d_in[5];
    const float* W_A2 = (const float*)d_in[6];
    const float* Wo   = (const float*)d_in[7];
    const float* bo   = (const float*)d_in[8];
    float* out = (float*)d_out;

    float* vp;     cudaGetSymbolAddress((void**)&vp,     g_vp);
    float* concat; cudaGetSymbolAddress((void**)&concat, g_concat);

    cudaFuncSetAttribute(fused_attn_kernel,
                         cudaFuncAttributeMaxDynamicSharedMemorySize, SMEM_FUSED);

    compute_L_kernel<<<H_, 256>>>(W_A, W_A2);
    xy_kernel<<<B_*S_, 512>>>(q, W_A2);
    sgemm_nn_bias<<<dim3(D_/128, (B_*S_)/128), 256>>>(B_*S_, D_, D_, v, Wv, bv, vp);
    fused_attn_kernel<<<dim3(S_/64, BH_), 256, SMEM_FUSED>>>();
    sgemm_nn_bias<<<dim3(D_/128, (B_*S_)/128), 256>>>(B_*S_, D_, D_, concat, Wo, bo, out);
}

// round 11
// speedup vs baseline: 1.0640x; 1.0640x over previous
#include <cuda_runtime.h>
#include <math.h>
#include <stddef.h>
#include <stdint.h>

// Problem constants
#define B_  2
#define S_  2048
#define D_  1024
#define H_  16
#define FK_ 32
#define DK_ 64
#define BH_ (B_*H_)

// ---------------- scratch (__device__ globals; no allocation allowed) ----------------
__device__ float g_LT[H_*FK_*DK_];        // LT[h][j][c] = (Wa@Wb@Wa2)[c][j]
__device__ float g_vp[B_*S_*D_];          // v@Wv+bv
__device__ float g_concat[B_*S_*D_];      // attention output pre-Wo
__device__ float g_X[BH_*S_*FK_];         // X[bh][s][32] = q.L
__device__ float g_Y[BH_*S_*FK_];         // Y[bh][t][32] = q.R^T

// ---------------- 1) collapse Wa@Wb@Wa2 per head (fp32) ----------------
__global__ void compute_L_kernel(const float* __restrict__ W_A,
                                 const float* __restrict__ W_A2) {
    int h = blockIdx.x;
    __shared__ float T1[64*64];
    const float* WAh  = W_A  + h*2048;
    const float* WA2h = W_A2 + h*2048;

    for (int idx = threadIdx.x; idx < 4096; idx += blockDim.x) {
        int c = idx >> 6, d = idx & 63;
        float acc = 0.f;
        #pragma unroll 8
        for (int j = 0; j < 32; j++)
            acc = fmaf(WAh[c*32 + j], WAh[j*64 + d], acc);
        T1[idx] = acc;
    }
    __syncthreads();
    for (int idx = threadIdx.x; idx < 2048; idx += blockDim.x) {
        int c = idx >> 5, j = idx & 31;
        float acc = 0.f;
        #pragma unroll 8
        for (int d = 0; d < 64; d++)
            acc = fmaf(T1[c*64 + d], WA2h[d*32 + j], acc);
        g_LT[h*2048 + j*64 + c] = acc;    // transposed for coalesced xy reads
    }
}

// ---------------- 2) X = q.L, Y = q.R^T per head (rank-32 factors) ----------------
__global__ __launch_bounds__(512)
void xy_kernel(const float* __restrict__ q, const float* __restrict__ W_A2) {
    int token = blockIdx.x;                  // b*2048+s
    int b = token >> 11, s = token & 2047;
    __shared__ float qs[D_];
    const float* qrow = q + (size_t)token * D_;
    for (int i = threadIdx.x; i < D_; i += 512) qs[i] = qrow[i];
    __syncthreads();
    int j = threadIdx.x & 31;
    int h = threadIdx.x >> 5;               // 0..15
    const float* qh = qs + h*64;
    const float* LTh = g_LT + h*2048 + j*64;  // contiguous 64 floats
    float x = 0.f;
    #pragma unroll 8
    for (int c = 0; c < 64; c++) x = fmaf(qh[c], LTh[c], x);
    const float* Rh = W_A2 + h*2048 + j*64;   // Wb2[h][j][d]
    float y = 0.f;
    #pragma unroll 8
    for (int d = 0; d < 64; d++) y = fmaf(qh[d], Rh[d], y);
    size_t o = (((size_t)(b*16 + h))*2048 + s)*32 + j;
    g_X[o] = x;
    g_Y[o] = y;
}

// ---------------- 3) scalar SGEMM (at SIMT fp32 issue ceiling) ----------------
__global__ __launch_bounds__(256)
void sgemm_nn_bias(int M, int N, int K,
                   const float* __restrict__ A,
                   const float* __restrict__ Bm,
                   const float* __restrict__ bias,
                   float* __restrict__ C) {
    __shared__ float As[16][128];
    __shared__ float Bs[16][128];
    int bm = blockIdx.y * 128;
    int bn = blockIdx.x * 128;
    int tid = threadIdx.x;
    int tx = tid & 15, ty = tid >> 4;

    float acc[8][8];
    #pragma unroll
    for (int i = 0; i < 8; i++)
        #pragma unroll
        for (int j = 0; j < 8; j++) acc[i][j] = 0.f;

    int arow = tid >> 1;
    int acol = (tid & 1) * 8;
    int brow = tid >> 4;
    int bcol = (tid & 15) * 8;

    for (int k0 = 0; k0 < K; k0 += 16) {
        const float* Ap = A + (size_t)(bm + arow) * K + k0 + acol;
        float4 a0 = *(const float4*)Ap;
        float4 a1 = *(const float4*)(Ap + 4);
        As[acol+0][arow] = a0.x; As[acol+1][arow] = a0.y;
        As[acol+2][arow] = a0.z; As[acol+3][arow] = a0.w;
        As[acol+4][arow] = a1.x; As[acol+5][arow] = a1.y;
        As[acol+6][arow] = a1.z; As[acol+7][arow] = a1.w;

        const float* Bp = Bm + (size_t)(k0 + brow) * N + bn + bcol;
        *(float4*)&Bs[brow][bcol]     = *(const float4*)Bp;
        *(float4*)&Bs[brow][bcol + 4] = *(const float4*)(Bp + 4);
        __syncthreads();

        #pragma unroll
        for (int kk = 0; kk < 16; kk++) {
            float a[8], b[8];
            *(float4*)(a)     = *(float4*)&As[kk][ty*8];
            *(float4*)(a + 4) = *(float4*)&As[kk][ty*8 + 4];
            *(float4*)(b)     = *(float4*)&Bs[kk][tx*8];
            *(float4*)(b + 4) = *(float4*)&Bs[kk][tx*8 + 4];
            #pragma unroll
            for (int i = 0; i < 8; i++)
                #pragma unroll
                for (int j = 0; j < 8; j++)
                    acc[i][j] = fmaf(a[i], b[j], acc[i][j]);
        }
        __syncthreads();
    }

    #pragma unroll
    for (int i = 0; i < 8; i++) {
        int row = bm + ty*8 + i;
        float* Cp = C + (size_t)row * N + bn + tx*8;
        float o[8];
        #pragma unroll
        for (int j = 0; j < 8; j++)
            o[j] = acc[i][j] + bias[bn + tx*8 + j];
        *(float4*)(Cp)     = *(float4*)(o);
        *(float4*)(Cp + 4) = *(float4*)(o + 4);
    }
}

// ---------------- 4) FUSED: scores + online softmax + sparse PV + TILE SKIP --------
// 64-row stripes, 3 CTA/SM. New vs R10: per-row tile-max computed in-register
// (butterfly over the 16 tx lanes) right after the GEMM; a row's spill AND scan
// for this tile are skipped when tilemax <= m_row - 95 -- bit-exact, since every
// skipped element would take the (dx > -95)-false branch (no contribution, no
// max update). m_row is mirrored to smem by scan threads (sub==0) each tile.
#define SCS 132
#define SM_B    8192
#define SM_SC   24576
#define SM_RMX  (SM_SC + 64*SCS*4)        // [64] per-row tile max
#define SM_MROW (SM_RMX + 256)            // [64] per-row running m
#define SMEM_FUSED (SM_MROW + 256)

__global__ __launch_bounds__(256, 3)
void fused_attn_kernel() {
    extern __shared__ __align__(128) char sm[];
    float* As  = (float*)(sm);            // [32][64]   As[k][row]
    float* Bs  = (float*)(sm + SM_B);     // [32][128]  Bs[k][col]
    float* SC  = (float*)(sm + SM_SC);    // [64][SCS]
    float* RMX = (float*)(sm + SM_RMX);   // [64]
    float* MRW = (float*)(sm + SM_MROW);  // [64]

    int tid = threadIdx.x;
    int stile = blockIdx.x, bh = blockIdx.y;
    int b = bh >> 4, h = bh & 15;
    int s0 = stile * 64;
    int tx = tid & 15, ty = tid >> 4;

    const float* X = g_X + ((size_t)bh*2048 + s0)*32;
    const float* Y = g_Y + (size_t)bh*2048*32;

    const float NEG_INF = __int_as_float(0xff800000);
    if (tid < 64) MRW[tid] = NEG_INF;

    // ---- stage A (transposed) once ----
    {
        int arow = tid >> 2, aq = tid & 3;
        const float4* xr = (const float4*)(X + arow*32 + aq*8);
        float4 v0 = xr[0], v1 = xr[1];
        int k0 = aq*8;
        As[(k0+0)*64+arow]=v0.x; As[(k0+1)*64+arow]=v0.y;
        As[(k0+2)*64+arow]=v0.z; As[(k0+3)*64+arow]=v0.w;
        As[(k0+4)*64+arow]=v1.x; As[(k0+5)*64+arow]=v1.y;
        As[(k0+6)*64+arow]=v1.z; As[(k0+7)*64+arow]=v1.w;
    }

    // ---- scan/PV state: row rt = tid>>2, dim chunk sub = tid&3 (16 dims) ----
    int rt = tid >> 2, sub = tid & 3;
    const float* vbase = g_vp + (size_t)b*2048*D_ + h*64 + sub*16;
    float m   = NEG_INF;
    float den = 0.f;
    float4 o4[4];
    #pragma unroll
    for (int jj = 0; jj < 4; jj++) o4[jj] = make_float4(0.f, 0.f, 0.f, 0.f);

    int brow = tid >> 1, bhalf = tid & 1;

    for (int tt = 0; tt < 16; tt++) {
        int t0 = tt * 128;
        // stage B tile (transposed)
        {
            const float4* yr = (const float4*)(Y + (size_t)(t0 + brow)*32 + bhalf*16);
            float4 v0 = yr[0], v1 = yr[1], v2 = yr[2], v3 = yr[3];
            int k0 = bhalf*16;
            Bs[(k0+ 0)*128+brow]=v0.x; Bs[(k0+ 1)*128+brow]=v0.y;
            Bs[(k0+ 2)*128+brow]=v0.z; Bs[(k0+ 3)*128+brow]=v0.w;
            Bs[(k0+ 4)*128+brow]=v1.x; Bs[(k0+ 5)*128+brow]=v1.y;
            Bs[(k0+ 6)*128+brow]=v1.z; Bs[(k0+ 7)*128+brow]=v1.w;
            Bs[(k0+ 8)*128+brow]=v2.x; Bs[(k0+ 9)*128+brow]=v2.y;
            Bs[(k0+10)*128+brow]=v2.z; Bs[(k0+11)*128+brow]=v2.w;
            Bs[(k0+12)*128+brow]=v3.x; Bs[(k0+13)*128+brow]=v3.y;
            Bs[(k0+14)*128+brow]=v3.z; Bs[(k0+15)*128+brow]=v3.w;
        }
        __syncthreads();

        // ---- 64x128 GEMM tile, 4x8 microtile ----
        float acc[4][8];
        #pragma unroll
        for (int i = 0; i < 4; i++)
            #pragma unroll
            for (int j = 0; j < 8; j++) acc[i][j] = 0.f;

        #pragma unroll
        for (int kk = 0; kk < 32; kk++) {
            float a[4], bb[8];
            *(float4*)(a)      = *(float4*)&As[kk*64 + ty*4];
            *(float4*)(bb)     = *(float4*)&Bs[kk*128 + tx*8];
            *(float4*)(bb + 4) = *(float4*)&Bs[kk*128 + tx*8 + 4];
            #pragma unroll
            for (int i = 0; i < 4; i++)
                #pragma unroll
                for (int j = 0; j < 8; j++)
                    acc[i][j] = fmaf(a[i], bb[j], acc[i][j]);
        }

        // ---- per-row tile max: butterfly over the 16 tx lanes ----
        float rmx[4];
        #pragma unroll
        for (int i = 0; i < 4; i++) {
            float v = acc[i][0];
            #pragma unroll
            for (int j = 1; j < 8; j++) v = fmaxf(v, acc[i][j]);
            rmx[i] = v;
        }
        #pragma unroll
        for (int msk = 1; msk < 16; msk <<= 1)
            #pragma unroll
            for (int i = 0; i < 4; i++)
                rmx[i] = fmaxf(rmx[i], __shfl_xor_sync(0xFFFFFFFFu, rmx[i], msk));
        if (tx == 0) {
            #pragma unroll
            for (int i = 0; i < 4; i++) RMX[ty*4 + i] = rmx[i];
        }

        // ---- spill only rows that will be scanned (uses m as of prev tile) ----
        #pragma unroll
        for (int i = 0; i < 4; i++) {
            if (rmx[i] > MRW[ty*4 + i] - 95.0f) {
                *(float4*)&SC[(ty*4+i)*SCS + tx*8]     = *(float4*)&acc[i][0];
                *(float4*)&SC[(ty*4+i)*SCS + tx*8 + 4] = *(float4*)&acc[i][4];
            }
        }
        __syncthreads();

        // ---- scan (skip whole tile-row if nothing can contribute) ----
        if (RMX[rt] > m - 95.0f) {
            const float* rp = SC + rt*SCS;
            #pragma unroll 4
            for (int j4 = 0; j4 < 32; j4++) {
                float4 x4 = *(const float4*)(rp + j4*4);
                float xs[4] = {x4.x, x4.y, x4.z, x4.w};
                #pragma unroll
                for (int u = 0; u < 4; u++) {
                    float x = xs[u];
                    int t = t0 + j4*4 + u;
                    if (x > m) {
                        float r = __expf(m - x);
                        den = den * r + 1.f;
                        const float4* vr = (const float4*)(vbase + (size_t)t * D_);
                        #pragma unroll
                        for (int jj = 0; jj < 4; jj++) {
                            float4 v = vr[jj];
                            o4[jj].x = fmaf(o4[jj].x, r, v.x);
                            o4[jj].y = fmaf(o4[jj].y, r, v.y);
                            o4[jj].z = fmaf(o4[jj].z, r, v.z);
                            o4[jj].w = fmaf(o4[jj].w, r, v.w);
                        }
                        m = x;
                    } else {
                        float dx = x - m;
                        if (dx > -95.0f) {
                            float w = __expf(dx);
                            den += w;
                            const float4* vr = (const float4*)(vbase + (size_t)t * D_);
                            #pragma unroll
                            for (int jj = 0; jj < 4; jj++) {
                                float4 v = vr[jj];
                                o4[jj].x = fmaf(w, v.x, o4[jj].x);
                                o4[jj].y = fmaf(w, v.y, o4[jj].y);
                                o4[jj].z = fmaf(w, v.z, o4[jj].z);
                                o4[jj].w = fmaf(w, v.w, o4[jj].w);
                            }
                        }
                    }
                }
            }
            if (sub == 0) MRW[rt] = m;   // mirror running max for next tile's skip
        }
        __syncthreads();   // scan + MRW update done before next spill / B restage
    }

    // ---- write out: o/den -> concat[b, s0+rt, h*64 + sub*16 ..] ----
    float inv = 1.f / den;
    float* op = g_concat + ((size_t)(b*2048 + s0 + rt))*D_ + h*64 + sub*16;
    #pragma unroll
    for (int jj = 0; jj < 4; jj++) {
        float4 r = o4[jj];
        r.x *= inv; r.y *= inv; r.z *= inv; r.w *= inv;
        *(float4*)(op + jj*4) = r;
    }
}

// ---------------- launcher ----------------
extern "C" void kernel_launch(void* const* d_in, const int* in_sizes, int n_in,
                              void* d_out, int out_size) {
    const float* q    = (const float*)d_in[0];
    // d_in[1] = k (unused in reference forward)
    const float* v    = (const float*)d_in[2];
    const float* Wv   = (const float*)d_in[3];
    const float* bv   = (const float*)d_in[4];
    const float* W_A  = (const float*)d_in[5];
    const float* W_A2 = (const float*)d_in[6];
    const float* Wo   = (const float*)d_in[7];
    const float* bo   = (const float*)d_in[8];
    float* out = (float*)d_out;

    float* vp;     cudaGetSymbolAddress((void**)&vp,     g_vp);
    float* concat; cudaGetSymbolAddress((void**)&concat, g_concat);

    cudaFuncSetAttribute(fused_attn_kernel,
                         cudaFuncAttributeMaxDynamicSharedMemorySize, SMEM_FUSED);

    compute_L_kernel<<<H_, 256>>>(W_A, W_A2);
    xy_kernel<<<B_*S_, 512>>>(q, W_A2);
    sgemm_nn_bias<<<dim3(D_/128, (B_*S_)/128), 256>>>(B_*S_, D_, D_, v, Wv, bv, vp);
    fused_attn_kernel<<<dim3(S_/64, BH_), 256, SMEM_FUSED>>>();
    sgemm_nn_bias<<<dim3(D_/128, (B_*S_)/128), 256>>>(B_*S_, D_, D_, concat, Wo, bo, out);
}

// round 12
// speedup vs baseline: 2.0061x; 1.8854x over previous
#include <cuda_runtime.h>
#include <math.h>
#include <stddef.h>
#include <stdint.h>

// Problem constants
#define B_  2
#define S_  2048
#define D_  1024
#define H_  16
#define FK_ 32
#define DK_ 64
#define BH_ (B_*H_)

// ---------------- scratch (__device__ globals; no allocation allowed) ----------------
__device__ float g_L [H_*DK_*FK_];        // L[h][c*32+j]  (j fastest -> warp-coalesced)
__device__ float g_RT[H_*DK_*FK_];        // RT[h][d*32+j] = Wb2[h][j][d]
__device__ float g_vp[B_*S_*D_];          // v@Wv+bv
__device__ float g_concat[B_*S_*D_];      // attention output pre-Wo
__device__ float g_X[BH_*S_*FK_];         // X[bh][s][32] = q.L
__device__ float g_Y[BH_*S_*FK_];         // Y[bh][t][32] = q.R^T

// ---------------- 1) collapse Wa@Wb@Wa2 per head (fp32) + RT transpose ----------
__global__ void compute_L_kernel(const float* __restrict__ W_A,
                                 const float* __restrict__ W_A2) {
    int h = blockIdx.x;
    __shared__ float T1[64*64];
    const float* WAh  = W_A  + h*2048;
    const float* WA2h = W_A2 + h*2048;

    for (int idx = threadIdx.x; idx < 4096; idx += blockDim.x) {
        int c = idx >> 6, d = idx & 63;
        float acc = 0.f;
        #pragma unroll 8
        for (int j = 0; j < 32; j++)
            acc = fmaf(WAh[c*32 + j], WAh[j*64 + d], acc);
        T1[idx] = acc;
    }
    __syncthreads();
    for (int idx = threadIdx.x; idx < 2048; idx += blockDim.x) {
        int c = idx >> 5, j = idx & 31;
        float acc = 0.f;
        #pragma unroll 8
        for (int d = 0; d < 64; d++)
            acc = fmaf(T1[c*64 + d], WA2h[d*32 + j], acc);
        g_L[h*2048 + c*32 + j] = acc;               // j fastest
    }
    // RT[h][d*32+j] = Wb2[h][j][d] = W_A2[h*2048 + j*64 + d]
    for (int idx = threadIdx.x; idx < 2048; idx += blockDim.x) {
        int d = idx >> 5, j = idx & 31;
        g_RT[h*2048 + d*32 + j] = WA2h[j*64 + d];
    }
}

// ---------------- 2) X = q.L, Y = q.R^T per head (warp-coalesced loads) ----------
__global__ __launch_bounds__(512)
void xy_kernel(const float* __restrict__ q) {
    int token = blockIdx.x;                  // b*2048+s
    int b = token >> 11, s = token & 2047;
    __shared__ float qs[D_];
    const float* qrow = q + (size_t)token * D_;
    for (int i = threadIdx.x; i < D_; i += 512) qs[i] = qrow[i];
    __syncthreads();
    int j = threadIdx.x & 31;
    int h = threadIdx.x >> 5;               // 0..15
    const float* qh = qs + h*64;
    const float* Lh  = g_L  + h*2048 + j;    // warp: 32 consecutive floats per iter
    const float* RTh = g_RT + h*2048 + j;
    float x = 0.f, y = 0.f;
    #pragma unroll 8
    for (int c = 0; c < 64; c++) x = fmaf(qh[c], Lh[c*32], x);
    #pragma unroll 8
    for (int d = 0; d < 64; d++) y = fmaf(qh[d], RTh[d*32], y);
    size_t o = (((size_t)(b*16 + h))*2048 + s)*32 + j;
    g_X[o] = x;
    g_Y[o] = y;
}

// ---------------- 3) scalar SGEMM (at SIMT fp32 issue ceiling) ----------------
__global__ __launch_bounds__(256)
void sgemm_nn_bias(int M, int N, int K,
                   const float* __restrict__ A,
                   const float* __restrict__ Bm,
                   const float* __restrict__ bias,
                   float* __restrict__ C) {
    __shared__ float As[16][128];
    __shared__ float Bs[16][128];
    int bm = blockIdx.y * 128;
    int bn = blockIdx.x * 128;
    int tid = threadIdx.x;
    int tx = tid & 15, ty = tid >> 4;

    float acc[8][8];
    #pragma unroll
    for (int i = 0; i < 8; i++)
        #pragma unroll
        for (int j = 0; j < 8; j++) acc[i][j] = 0.f;

    int arow = tid >> 1;
    int acol = (tid & 1) * 8;
    int brow = tid >> 4;
    int bcol = (tid & 15) * 8;

    for (int k0 = 0; k0 < K; k0 += 16) {
        const float* Ap = A + (size_t)(bm + arow) * K + k0 + acol;
        float4 a0 = *(const float4*)Ap;
        float4 a1 = *(const float4*)(Ap + 4);
        As[acol+0][arow] = a0.x; As[acol+1][arow] = a0.y;
        As[acol+2][arow] = a0.z; As[acol+3][arow] = a0.w;
        As[acol+4][arow] = a1.x; As[acol+5][arow] = a1.y;
        As[acol+6][arow] = a1.z; As[acol+7][arow] = a1.w;

        const float* Bp = Bm + (size_t)(k0 + brow) * N + bn + bcol;
        *(float4*)&Bs[brow][bcol]     = *(const float4*)Bp;
        *(float4*)&Bs[brow][bcol + 4] = *(const float4*)(Bp + 4);
        __syncthreads();

        #pragma unroll
        for (int kk = 0; kk < 16; kk++) {
            float a[8], b[8];
            *(float4*)(a)     = *(float4*)&As[kk][ty*8];
            *(float4*)(a + 4) = *(float4*)&As[kk][ty*8 + 4];
            *(float4*)(b)     = *(float4*)&Bs[kk][tx*8];
            *(float4*)(b + 4) = *(float4*)&Bs[kk][tx*8 + 4];
            #pragma unroll
            for (int i = 0; i < 8; i++)
                #pragma unroll
                for (int j = 0; j < 8; j++)
                    acc[i][j] = fmaf(a[i], b[j], acc[i][j]);
        }
        __syncthreads();
    }

    #pragma unroll
    for (int i = 0; i < 8; i++) {
        int row = bm + ty*8 + i;
        float* Cp = C + (size_t)row * N + bn + tx*8;
        float o[8];
        #pragma unroll
        for (int j = 0; j < 8; j++)
            o[j] = acc[i][j] + bias[bn + tx*8 + j];
        *(float4*)(Cp)     = *(float4*)(o);
        *(float4*)(Cp + 4) = *(float4*)(o + 4);
    }
}

// ---------------- 4) FUSED: scores + online softmax + sparse PV + TILE SKIP --------
// Identical to R11 (measured 478us, bit-exact skip logic).
#define SCS 132
#define SM_B    8192
#define SM_SC   24576
#define SM_RMX  (SM_SC + 64*SCS*4)        // [64] per-row tile max
#define SM_MROW (SM_RMX + 256)            // [64] per-row running m
#define SMEM_FUSED (SM_MROW + 256)

__global__ __launch_bounds__(256, 3)
void fused_attn_kernel() {
    extern __shared__ __align__(128) char sm[];
    float* As  = (float*)(sm);            // [32][64]   As[k][row]
    float* Bs  = (float*)(sm + SM_B);     // [32][128]  Bs[k][col]
    float* SC  = (float*)(sm + SM_SC);    // [64][SCS]
    float* RMX = (float*)(sm + SM_RMX);   // [64]
    float* MRW = (float*)(sm + SM_MROW);  // [64]

    int tid = threadIdx.x;
    int stile = blockIdx.x, bh = blockIdx.y;
    int b = bh >> 4, h = bh & 15;
    int s0 = stile * 64;
    int tx = tid & 15, ty = tid >> 4;

    const float* X = g_X + ((size_t)bh*2048 + s0)*32;
    const float* Y = g_Y + (size_t)bh*2048*32;

    const float NEG_INF = __int_as_float(0xff800000);
    if (tid < 64) MRW[tid] = NEG_INF;

    // ---- stage A (transposed) once ----
    {
        int arow = tid >> 2, aq = tid & 3;
        const float4* xr = (const float4*)(X + arow*32 + aq*8);
        float4 v0 = xr[0], v1 = xr[1];
        int k0 = aq*8;
        As[(k0+0)*64+arow]=v0.x; As[(k0+1)*64+arow]=v0.y;
        As[(k0+2)*64+arow]=v0.z; As[(k0+3)*64+arow]=v0.w;
        As[(k0+4)*64+arow]=v1.x; As[(k0+5)*64+arow]=v1.y;
        As[(k0+6)*64+arow]=v1.z; As[(k0+7)*64+arow]=v1.w;
    }

    // ---- scan/PV state: row rt = tid>>2, dim chunk sub = tid&3 (16 dims) ----
    int rt = tid >> 2, sub = tid & 3;
    const float* vbase = g_vp + (size_t)b*2048*D_ + h*64 + sub*16;
    float m   = NEG_INF;
    float den = 0.f;
    float4 o4[4];
    #pragma unroll
    for (int jj = 0; jj < 4; jj++) o4[jj] = make_float4(0.f, 0.f, 0.f, 0.f);

    int brow = tid >> 1, bhalf = tid & 1;

    for (int tt = 0; tt < 16; tt++) {
        int t0 = tt * 128;
        // stage B tile (transposed)
        {
            const float4* yr = (const float4*)(Y + (size_t)(t0 + brow)*32 + bhalf*16);
            float4 v0 = yr[0], v1 = yr[1], v2 = yr[2], v3 = yr[3];
            int k0 = bhalf*16;
            Bs[(k0+ 0)*128+brow]=v0.x; Bs[(k0+ 1)*128+brow]=v0.y;
            Bs[(k0+ 2)*128+brow]=v0.z; Bs[(k0+ 3)*128+brow]=v0.w;
            Bs[(k0+ 4)*128+brow]=v1.x; Bs[(k0+ 5)*128+brow]=v1.y;
            Bs[(k0+ 6)*128+brow]=v1.z; Bs[(k0+ 7)*128+brow]=v1.w;
            Bs[(k0+ 8)*128+brow]=v2.x; Bs[(k0+ 9)*128+brow]=v2.y;
            Bs[(k0+10)*128+brow]=v2.z; Bs[(k0+11)*128+brow]=v2.w;
            Bs[(k0+12)*128+brow]=v3.x; Bs[(k0+13)*128+brow]=v3.y;
            Bs[(k0+14)*128+brow]=v3.z; Bs[(k0+15)*128+brow]=v3.w;
        }
        __syncthreads();

        // ---- 64x128 GEMM tile, 4x8 microtile ----
        float acc[4][8];
        #pragma unroll
        for (int i = 0; i < 4; i++)
            #pragma unroll
            for (int j = 0; j < 8; j++) acc[i][j] = 0.f;

        #pragma unroll
        for (int kk = 0; kk < 32; kk++) {
            float a[4], bb[8];
            *(float4*)(a)      = *(float4*)&As[kk*64 + ty*4];
            *(float4*)(bb)     = *(float4*)&Bs[kk*128 + tx*8];
            *(float4*)(bb + 4) = *(float4*)&Bs[kk*128 + tx*8 + 4];
            #pragma unroll
            for (int i = 0; i < 4; i++)
                #pragma unroll
                for (int j = 0; j < 8; j++)
                    acc[i][j] = fmaf(a[i], bb[j], acc[i][j]);
        }

        // ---- per-row tile max: butterfly over the 16 tx lanes ----
        float rmx[4];
        #pragma unroll
        for (int i = 0; i < 4; i++) {
            float v = acc[i][0];
            #pragma unroll
            for (int j = 1; j < 8; j++) v = fmaxf(v, acc[i][j]);
            rmx[i] = v;
        }
        #pragma unroll
        for (int msk = 1; msk < 16; msk <<= 1)
            #pragma unroll
            for (int i = 0; i < 4; i++)
                rmx[i] = fmaxf(rmx[i], __shfl_xor_sync(0xFFFFFFFFu, rmx[i], msk));
        if (tx == 0) {
            #pragma unroll
            for (int i = 0; i < 4; i++) RMX[ty*4 + i] = rmx[i];
        }

        // ---- spill only rows that will be scanned ----
        #pragma unroll
        for (int i = 0; i < 4; i++) {
            if (rmx[i] > MRW[ty*4 + i] - 95.0f) {
                *(float4*)&SC[(ty*4+i)*SCS + tx*8]     = *(float4*)&acc[i][0];
                *(float4*)&SC[(ty*4+i)*SCS + tx*8 + 4] = *(float4*)&acc[i][4];
            }
        }
        __syncthreads();

        // ---- scan (skip whole tile-row if nothing can contribute) ----
        if (RMX[rt] > m - 95.0f) {
            const float* rp = SC + rt*SCS;
            #pragma unroll 4
            for (int j4 = 0; j4 < 32; j4++) {
                float4 x4 = *(const float4*)(rp + j4*4);
                float xs[4] = {x4.x, x4.y, x4.z, x4.w};
                #pragma unroll
                for (int u = 0; u < 4; u++) {
                    float x = xs[u];
                    int t = t0 + j4*4 + u;
                    if (x > m) {
                        float r = __expf(m - x);
                        den = den * r + 1.f;
                        const float4* vr = (const float4*)(vbase + (size_t)t * D_);
                        #pragma unroll
                        for (int jj = 0; jj < 4; jj++) {
                            float4 v = vr[jj];
                            o4[jj].x = fmaf(o4[jj].x, r, v.x);
                            o4[jj].y = fmaf(o4[jj].y, r, v.y);
                            o4[jj].z = fmaf(o4[jj].z, r, v.z);
                            o4[jj].w = fmaf(o4[jj].w, r, v.w);
                        }
                        m = x;
                    } else {
                        float dx = x - m;
                        if (dx > -95.0f) {
                            float w = __expf(dx);
                            den += w;
                            const float4* vr = (const float4*)(vbase + (size_t)t * D_);
                            #pragma unroll
                            for (int jj = 0; jj < 4; jj++) {
                                float4 v = vr[jj];
                                o4[jj].x = fmaf(w, v.x, o4[jj].x);
                                o4[jj].y = fmaf(w, v.y, o4[jj].y);
                                o4[jj].z = fmaf(w, v.z, o4[jj].z);
                                o4[jj].w = fmaf(w, v.w, o4[jj].w);
                            }
                        }
                    }
                }
            }
            if (sub == 0) MRW[rt] = m;   // mirror running max for next tile's skip
        }
        __syncthreads();   // scan + MRW update done before next spill / B restage
    }

    // ---- write out: o/den -> concat[b, s0+rt, h*64 + sub*16 ..] ----
    float inv = 1.f / den;
    float* op = g_concat + ((size_t)(b*2048 + s0 + rt))*D_ + h*64 + sub*16;
    #pragma unroll
    for (int jj = 0; jj < 4; jj++) {
        float4 r = o4[jj];
        r.x *= inv; r.y *= inv; r.z *= inv; r.w *= inv;
        *(float4*)(op + jj*4) = r;
    }
}

// ---------------- launcher ----------------
extern "C" void kernel_launch(void* const* d_in, const int* in_sizes, int n_in,
                              void* d_out, int out_size) {
    const float* q    = (const float*)d_in[0];
    // d_in[1] = k (unused in reference forward)
    const float* v    = (const float*)d_in[2];
    const float* Wv   = (const float*)d_in[3];
    const float* bv   = (const float*)d_in[4];
    const float* W_A  = (const float*)d_in[5];
    const float* W_A2 = (const float*)d_in[6];
    const float* Wo   = (const float*)d_in[7];
    const float* bo   = (const float*)d_in[8];
    float* out = (float*)d_out;

    float* vp;     cudaGetSymbolAddress((void**)&vp,     g_vp);
    float* concat; cudaGetSymbolAddress((void**)&concat, g_concat);

    cudaFuncSetAttribute(fused_attn_kernel,
                         cudaFuncAttributeMaxDynamicSharedMemorySize, SMEM_FUSED);

    compute_L_kernel<<<H_, 256>>>(W_A, W_A2);
    xy_kernel<<<B_*S_, 512>>>(q);
    sgemm_nn_bias<<<dim3(D_/128, (B_*S_)/128), 256>>>(B_*S_, D_, D_, v, Wv, bv, vp);
    fused_attn_kernel<<<dim3(S_/64, BH_), 256, SMEM_FUSED>>>();
    sgemm_nn_bias<<<dim3(D_/128, (B_*S_)/128), 256>>>(B_*S_, D_, D_, concat, Wo, bo, out);
}

// round 13
// speedup vs baseline: 2.1426x; 1.0680x over previous
#include <cuda_runtime.h>
#include <math.h>
#include <stddef.h>
#include <stdint.h>

// Problem constants
#define B_  2
#define S_  2048
#define D_  1024
#define H_  16
#define FK_ 32
#define DK_ 64
#define BH_ (B_*H_)

// ---------------- scratch (__device__ globals; no allocation allowed) ----------------
__device__ float g_L [H_*DK_*FK_];        // L[h][c*32+j]  (j fastest -> warp-coalesced)
__device__ float g_RT[H_*DK_*FK_];        // RT[h][d*32+j] = Wb2[h][j][d]
__device__ float g_vp[B_*S_*D_];          // v@Wv+bv
__device__ float g_concat[B_*S_*D_];      // attention output pre-Wo
__device__ float g_X[BH_*S_*FK_];         // X[bh][s][32] = q.L
__device__ float g_Y[BH_*S_*FK_];         // Y[bh][t][32] = q.R^T

// ---------------- 1) collapse Wa@Wb@Wa2 per head (fp32) + RT transpose ----------
__global__ void compute_L_kernel(const float* __restrict__ W_A,
                                 const float* __restrict__ W_A2) {
    int h = blockIdx.x;
    __shared__ float T1[64*64];
    const float* WAh  = W_A  + h*2048;
    const float* WA2h = W_A2 + h*2048;

    for (int idx = threadIdx.x; idx < 4096; idx += blockDim.x) {
        int c = idx >> 6, d = idx & 63;
        float acc = 0.f;
        #pragma unroll 8
        for (int j = 0; j < 32; j++)
            acc = fmaf(WAh[c*32 + j], WAh[j*64 + d], acc);
        T1[idx] = acc;
    }
    __syncthreads();
    for (int idx = threadIdx.x; idx < 2048; idx += blockDim.x) {
        int c = idx >> 5, j = idx & 31;
        float acc = 0.f;
        #pragma unroll 8
        for (int d = 0; d < 64; d++)
            acc = fmaf(T1[c*64 + d], WA2h[d*32 + j], acc);
        g_L[h*2048 + c*32 + j] = acc;               // j fastest
    }
    // RT[h][d*32+j] = Wb2[h][j][d] = W_A2[h*2048 + j*64 + d]
    for (int idx = threadIdx.x; idx < 2048; idx += blockDim.x) {
        int d = idx >> 5, j = idx & 31;
        g_RT[h*2048 + d*32 + j] = WA2h[j*64 + d];
    }
}

// ---------------- 2) X = q.L, Y = q.R^T per head (warp-coalesced loads) ----------
__global__ __launch_bounds__(512)
void xy_kernel(const float* __restrict__ q) {
    int token = blockIdx.x;                  // b*2048+s
    int b = token >> 11, s = token & 2047;
    __shared__ float qs[D_];
    const float* qrow = q + (size_t)token * D_;
    for (int i = threadIdx.x; i < D_; i += 512) qs[i] = qrow[i];
    __syncthreads();
    int j = threadIdx.x & 31;
    int h = threadIdx.x >> 5;               // 0..15
    const float* qh = qs + h*64;
    const float* Lh  = g_L  + h*2048 + j;    // warp: 32 consecutive floats per iter
    const float* RTh = g_RT + h*2048 + j;
    float x = 0.f, y = 0.f;
    #pragma unroll 8
    for (int c = 0; c < 64; c++) x = fmaf(qh[c], Lh[c*32], x);
    #pragma unroll 8
    for (int d = 0; d < 64; d++) y = fmaf(qh[d], RTh[d*32], y);
    size_t o = (((size_t)(b*16 + h))*2048 + s)*32 + j;
    g_X[o] = x;
    g_Y[o] = y;
}

// ---------------- 3) scalar SGEMM (at SIMT fp32 issue ceiling) ----------------
__global__ __launch_bounds__(256)
void sgemm_nn_bias(int M, int N, int K,
                   const float* __restrict__ A,
                   const float* __restrict__ Bm,
                   const float* __restrict__ bias,
                   float* __restrict__ C) {
    __shared__ float As[16][128];
    __shared__ float Bs[16][128];
    int bm = blockIdx.y * 128;
    int bn = blockIdx.x * 128;
    int tid = threadIdx.x;
    int tx = tid & 15, ty = tid >> 4;

    float acc[8][8];
    #pragma unroll
    for (int i = 0; i < 8; i++)
        #pragma unroll
        for (int j = 0; j < 8; j++) acc[i][j] = 0.f;

    int arow = tid >> 1;
    int acol = (tid & 1) * 8;
    int brow = tid >> 4;
    int bcol = (tid & 15) * 8;

    for (int k0 = 0; k0 < K; k0 += 16) {
        const float* Ap = A + (size_t)(bm + arow) * K + k0 + acol;
        float4 a0 = *(const float4*)Ap;
        float4 a1 = *(const float4*)(Ap + 4);
        As[acol+0][arow] = a0.x; As[acol+1][arow] = a0.y;
        As[acol+2][arow] = a0.z; As[acol+3][arow] = a0.w;
        As[acol+4][arow] = a1.x; As[acol+5][arow] = a1.y;
        As[acol+6][arow] = a1.z; As[acol+7][arow] = a1.w;

        const float* Bp = Bm + (size_t)(k0 + brow) * N + bn + bcol;
        *(float4*)&Bs[brow][bcol]     = *(const float4*)Bp;
        *(float4*)&Bs[brow][bcol + 4] = *(const float4*)(Bp + 4);
        __syncthreads();

        #pragma unroll
        for (int kk = 0; kk < 16; kk++) {
            float a[8], b[8];
            *(float4*)(a)     = *(float4*)&As[kk][ty*8];
            *(float4*)(a + 4) = *(float4*)&As[kk][ty*8 + 4];
            *(float4*)(b)     = *(float4*)&Bs[kk][tx*8];
            *(float4*)(b + 4) = *(float4*)&Bs[kk][tx*8 + 4];
            #pragma unroll
            for (int i = 0; i < 8; i++)
                #pragma unroll
                for (int j = 0; j < 8; j++)
                    acc[i][j] = fmaf(a[i], b[j], acc[i][j]);
        }
        __syncthreads();
    }

    #pragma unroll
    for (int i = 0; i < 8; i++) {
        int row = bm + ty*8 + i;
        float* Cp = C + (size_t)row * N + bn + tx*8;
        float o[8];
        #pragma unroll
        for (int j = 0; j < 8; j++)
            o[j] = acc[i][j] + bias[bn + tx*8 + j];
        *(float4*)(Cp)     = *(float4*)(o);
        *(float4*)(Cp + 4) = *(float4*)(o + 4);
    }
}

// ---------------- 4) FUSED: scores + online softmax + sparse PV + TILE SKIP --------
// R12 + QUAD SHORT-CIRCUIT in the scan: a float4 whose max is <= m-95 can
// neither contribute (every element takes the dx>-95 false branch) nor raise m
// (raising m needs x > m > m-95), so it is skipped in ~6 instructions. Bit-exact.
#define SCS 132
#define SM_B    8192
#define SM_SC   24576
#define SM_RMX  (SM_SC + 64*SCS*4)        // [64] per-row tile max
#define SM_MROW (SM_RMX + 256)            // [64] per-row running m
#define SMEM_FUSED (SM_MROW + 256)

__global__ __launch_bounds__(256, 3)
void fused_attn_kernel() {
    extern __shared__ __align__(128) char sm[];
    float* As  = (float*)(sm);            // [32][64]   As[k][row]
    float* Bs  = (float*)(sm + SM_B);     // [32][128]  Bs[k][col]
    float* SC  = (float*)(sm + SM_SC);    // [64][SCS]
    float* RMX = (float*)(sm + SM_RMX);   // [64]
    float* MRW = (float*)(sm + SM_MROW);  // [64]

    int tid = threadIdx.x;
    int stile = blockIdx.x, bh = blockIdx.y;
    int b = bh >> 4, h = bh & 15;
    int s0 = stile * 64;
    int tx = tid & 15, ty = tid >> 4;

    const float* X = g_X + ((size_t)bh*2048 + s0)*32;
    const float* Y = g_Y + (size_t)bh*2048*32;

    const float NEG_INF = __int_as_float(0xff800000);
    if (tid < 64) MRW[tid] = NEG_INF;

    // ---- stage A (transposed) once ----
    {
        int arow = tid >> 2, aq = tid & 3;
        const float4* xr = (const float4*)(X + arow*32 + aq*8);
        float4 v0 = xr[0], v1 = xr[1];
        int k0 = aq*8;
        As[(k0+0)*64+arow]=v0.x; As[(k0+1)*64+arow]=v0.y;
        As[(k0+2)*64+arow]=v0.z; As[(k0+3)*64+arow]=v0.w;
        As[(k0+4)*64+arow]=v1.x; As[(k0+5)*64+arow]=v1.y;
        As[(k0+6)*64+arow]=v1.z; As[(k0+7)*64+arow]=v1.w;
    }

    // ---- scan/PV state: row rt = tid>>2, dim chunk sub = tid&3 (16 dims) ----
    int rt = tid >> 2, sub = tid & 3;
    const float* vbase = g_vp + (size_t)b*2048*D_ + h*64 + sub*16;
    float m   = NEG_INF;
    float den = 0.f;
    float4 o4[4];
    #pragma unroll
    for (int jj = 0; jj < 4; jj++) o4[jj] = make_float4(0.f, 0.f, 0.f, 0.f);

    int brow = tid >> 1, bhalf = tid & 1;

    for (int tt = 0; tt < 16; tt++) {
        int t0 = tt * 128;
        // stage B tile (transposed)
        {
            const float4* yr = (const float4*)(Y + (size_t)(t0 + brow)*32 + bhalf*16);
            float4 v0 = yr[0], v1 = yr[1], v2 = yr[2], v3 = yr[3];
            int k0 = bhalf*16;
            Bs[(k0+ 0)*128+brow]=v0.x; Bs[(k0+ 1)*128+brow]=v0.y;
            Bs[(k0+ 2)*128+brow]=v0.z; Bs[(k0+ 3)*128+brow]=v0.w;
            Bs[(k0+ 4)*128+brow]=v1.x; Bs[(k0+ 5)*128+brow]=v1.y;
            Bs[(k0+ 6)*128+brow]=v1.z; Bs[(k0+ 7)*128+brow]=v1.w;
            Bs[(k0+ 8)*128+brow]=v2.x; Bs[(k0+ 9)*128+brow]=v2.y;
            Bs[(k0+10)*128+brow]=v2.z; Bs[(k0+11)*128+brow]=v2.w;
            Bs[(k0+12)*128+brow]=v3.x; Bs[(k0+13)*128+brow]=v3.y;
            Bs[(k0+14)*128+brow]=v3.z; Bs[(k0+15)*128+brow]=v3.w;
        }
        __syncthreads();

        // ---- 64x128 GEMM tile, 4x8 microtile ----
        float acc[4][8];
        #pragma unroll
        for (int i = 0; i < 4; i++)
            #pragma unroll
            for (int j = 0; j < 8; j++) acc[i][j] = 0.f;

        #pragma unroll
        for (int kk = 0; kk < 32; kk++) {
            float a[4], bb[8];
            *(float4*)(a)      = *(float4*)&As[kk*64 + ty*4];
            *(float4*)(bb)     = *(float4*)&Bs[kk*128 + tx*8];
            *(float4*)(bb + 4) = *(float4*)&Bs[kk*128 + tx*8 + 4];
            #pragma unroll
            for (int i = 0; i < 4; i++)
                #pragma unroll
                for (int j = 0; j < 8; j++)
                    acc[i][j] = fmaf(a[i], bb[j], acc[i][j]);
        }

        // ---- per-row tile max: butterfly over the 16 tx lanes ----
        float rmx[4];
        #pragma unroll
        for (int i = 0; i < 4; i++) {
            float v = acc[i][0];
            #pragma unroll
            for (int j = 1; j < 8; j++) v = fmaxf(v, acc[i][j]);
            rmx[i] = v;
        }
        #pragma unroll
        for (int msk = 1; msk < 16; msk <<= 1)
            #pragma unroll
            for (int i = 0; i < 4; i++)
                rmx[i] = fmaxf(rmx[i], __shfl_xor_sync(0xFFFFFFFFu, rmx[i], msk));
        if (tx == 0) {
            #pragma unroll
            for (int i = 0; i < 4; i++) RMX[ty*4 + i] = rmx[i];
        }

        // ---- spill only rows that will be scanned ----
        #pragma unroll
        for (int i = 0; i < 4; i++) {
            if (rmx[i] > MRW[ty*4 + i] - 95.0f) {
                *(float4*)&SC[(ty*4+i)*SCS + tx*8]     = *(float4*)&acc[i][0];
                *(float4*)&SC[(ty*4+i)*SCS + tx*8 + 4] = *(float4*)&acc[i][4];
            }
        }
        __syncthreads();

        // ---- scan (tile-row skip, then quad short-circuit) ----
        if (RMX[rt] > m - 95.0f) {
            const float* rp = SC + rt*SCS;
            #pragma unroll 4
            for (int j4 = 0; j4 < 32; j4++) {
                float4 x4 = *(const float4*)(rp + j4*4);
                float mx4 = fmaxf(fmaxf(x4.x, x4.y), fmaxf(x4.z, x4.w));
                if (mx4 <= m - 95.0f) continue;   // whole quad inert (bit-exact)
                float xs[4] = {x4.x, x4.y, x4.z, x4.w};
                #pragma unroll
                for (int u = 0; u < 4; u++) {
                    float x = xs[u];
                    int t = t0 + j4*4 + u;
                    if (x > m) {
                        float r = __expf(m - x);
                        den = den * r + 1.f;
                        const float4* vr = (const float4*)(vbase + (size_t)t * D_);
                        #pragma unroll
                        for (int jj = 0; jj < 4; jj++) {
                            float4 v = vr[jj];
                            o4[jj].x = fmaf(o4[jj].x, r, v.x);
                            o4[jj].y = fmaf(o4[jj].y, r, v.y);
                            o4[jj].z = fmaf(o4[jj].z, r, v.z);
                            o4[jj].w = fmaf(o4[jj].w, r, v.w);
                        }
                        m = x;
                    } else {
                        float dx = x - m;
                        if (dx > -95.0f) {
                            float w = __expf(dx);
                            den += w;
                            const float4* vr = (const float4*)(vbase + (size_t)t * D_);
                            #pragma unroll
                            for (int jj = 0; jj < 4; jj++) {
                                float4 v = vr[jj];
                                o4[jj].x = fmaf(w, v.x, o4[jj].x);
                                o4[jj].y = fmaf(w, v.y, o4[jj].y);
                                o4[jj].z = fmaf(w, v.z, o4[jj].z);
                                o4[jj].w = fmaf(w, v.w, o4[jj].w);
                            }
                        }
                    }
                }
            }
            if (sub == 0) MRW[rt] = m;   // mirror running max for next tile's skip
        }
        __syncthreads();   // scan + MRW update done before next spill / B restage
    }

    // ---- write out: o/den -> concat[b, s0+rt, h*64 + sub*16 ..] ----
    float inv = 1.f / den;
    float* op = g_concat + ((size_t)(b*2048 + s0 + rt))*D_ + h*64 + sub*16;
    #pragma unroll
    for (int jj = 0; jj < 4; jj++) {
        float4 r = o4[jj];
        r.x *= inv; r.y *= inv; r.z *= inv; r.w *= inv;
        *(float4*)(op + jj*4) = r;
    }
}

// ---------------- launcher ----------------
extern "C" void kernel_launch(void* const* d_in, const int* in_sizes, int n_in,
                              void* d_out, int out_size) {
    const float* q    = (const float*)d_in[0];
    // d_in[1] = k (unused in reference forward)
    const float* v    = (const float*)d_in[2];
    const float* Wv   = (const float*)d_in[3];
    const float* bv   = (const float*)d_in[4];
    const float* W_A  = (const float*)d_in[5];
    const float* W_A2 = (const float*)d_in[6];
    const float* Wo   = (const float*)d_in[7];
    const float* bo   = (const float*)d_in[8];
    float* out = (float*)d_out;

    float* vp;     cudaGetSymbolAddress((void**)&vp,     g_vp);
    float* concat; cudaGetSymbolAddress((void**)&concat, g_concat);

    cudaFuncSetAttribute(fused_attn_kernel,
                         cudaFuncAttributeMaxDynamicSharedMemorySize, SMEM_FUSED);

    compute_L_kernel<<<H_, 256>>>(W_A, W_A2);
    xy_kernel<<<B_*S_, 512>>>(q);
    sgemm_nn_bias<<<dim3(D_/128, (B_*S_)/128), 256>>>(B_*S_, D_, D_, v, Wv, bv, vp);
    fused_attn_kernel<<<dim3(S_/64, BH_), 256, SMEM_FUSED>>>();
    sgemm_nn_bias<<<dim3(D_/128, (B_*S_)/128), 256>>>(B_*S_, D_, D_, concat, Wo, bo, out);
}

// round 14
// speedup vs baseline: 2.4300x; 1.1341x over previous
#include <cuda_runtime.h>
#include <math.h>
#include <stddef.h>
#include <stdint.h>

// Problem constants
#define B_  2
#define S_  2048
#define D_  1024
#define H_  16
#define FK_ 32
#define DK_ 64
#define BH_ (B_*H_)

// ---------------- scratch (__device__ globals; no allocation allowed) ----------------
__device__ float g_L [H_*DK_*FK_];        // L[h][c*32+j]  (j fastest -> warp-coalesced)
__device__ float g_RT[H_*DK_*FK_];        // RT[h][d*32+j] = Wb2[h][j][d]
__device__ float g_vp[B_*S_*D_];          // v@Wv+bv
__device__ float g_concat[B_*S_*D_];      // attention output pre-Wo
__device__ float g_X[BH_*S_*FK_];         // X[bh][s][32] = q.L
__device__ float g_Y[BH_*S_*FK_];         // Y[bh][t][32] = q.R^T

// ---------------- 1) collapse Wa@Wb@Wa2 per head (fp32) + RT transpose ----------
__global__ void compute_L_kernel(const float* __restrict__ W_A,
                                 const float* __restrict__ W_A2) {
    int h = blockIdx.x;
    __shared__ float T1[64*64];
    const float* WAh  = W_A  + h*2048;
    const float* WA2h = W_A2 + h*2048;

    for (int idx = threadIdx.x; idx < 4096; idx += blockDim.x) {
        int c = idx >> 6, d = idx & 63;
        float acc = 0.f;
        #pragma unroll 8
        for (int j = 0; j < 32; j++)
            acc = fmaf(WAh[c*32 + j], WAh[j*64 + d], acc);
        T1[idx] = acc;
    }
    __syncthreads();
    for (int idx = threadIdx.x; idx < 2048; idx += blockDim.x) {
        int c = idx >> 5, j = idx & 31;
        float acc = 0.f;
        #pragma unroll 8
        for (int d = 0; d < 64; d++)
            acc = fmaf(T1[c*64 + d], WA2h[d*32 + j], acc);
        g_L[h*2048 + c*32 + j] = acc;               // j fastest
    }
    for (int idx = threadIdx.x; idx < 2048; idx += blockDim.x) {
        int d = idx >> 5, j = idx & 31;
        g_RT[h*2048 + d*32 + j] = WA2h[j*64 + d];
    }
}

// ---------------- 2) X = q.L, Y = q.R^T per head (warp-coalesced loads) ----------
__global__ __launch_bounds__(512)
void xy_kernel(const float* __restrict__ q) {
    int token = blockIdx.x;                  // b*2048+s
    int b = token >> 11, s = token & 2047;
    __shared__ float qs[D_];
    const float* qrow = q + (size_t)token * D_;
    for (int i = threadIdx.x; i < D_; i += 512) qs[i] = qrow[i];
    __syncthreads();
    int j = threadIdx.x & 31;
    int h = threadIdx.x >> 5;               // 0..15
    const float* qh = qs + h*64;
    const float* Lh  = g_L  + h*2048 + j;
    const float* RTh = g_RT + h*2048 + j;
    float x = 0.f, y = 0.f;
    #pragma unroll 8
    for (int c = 0; c < 64; c++) x = fmaf(qh[c], Lh[c*32], x);
    #pragma unroll 8
    for (int d = 0; d < 64; d++) y = fmaf(qh[d], RTh[d*32], y);
    size_t o = (((size_t)(b*16 + h))*2048 + s)*32 + j;
    g_X[o] = x;
    g_Y[o] = y;
}

// ---------------- 3) scalar SGEMM (at SIMT fp32 issue ceiling) ----------------
__global__ __launch_bounds__(256)
void sgemm_nn_bias(int M, int N, int K,
                   const float* __restrict__ A,
                   const float* __restrict__ Bm,
                   const float* __restrict__ bias,
                   float* __restrict__ C) {
    __shared__ float As[16][128];
    __shared__ float Bs[16][128];
    int bm = blockIdx.y * 128;
    int bn = blockIdx.x * 128;
    int tid = threadIdx.x;
    int tx = tid & 15, ty = tid >> 4;

    float acc[8][8];
    #pragma unroll
    for (int i = 0; i < 8; i++)
        #pragma unroll
        for (int j = 0; j < 8; j++) acc[i][j] = 0.f;

    int arow = tid >> 1;
    int acol = (tid & 1) * 8;
    int brow = tid >> 4;
    int bcol = (tid & 15) * 8;

    for (int k0 = 0; k0 < K; k0 += 16) {
        const float* Ap = A + (size_t)(bm + arow) * K + k0 + acol;
        float4 a0 = *(const float4*)Ap;
        float4 a1 = *(const float4*)(Ap + 4);
        As[acol+0][arow] = a0.x; As[acol+1][arow] = a0.y;
        As[acol+2][arow] = a0.z; As[acol+3][arow] = a0.w;
        As[acol+4][arow] = a1.x; As[acol+5][arow] = a1.y;
        As[acol+6][arow] = a1.z; As[acol+7][arow] = a1.w;

        const float* Bp = Bm + (size_t)(k0 + brow) * N + bn + bcol;
        *(float4*)&Bs[brow][bcol]     = *(const float4*)Bp;
        *(float4*)&Bs[brow][bcol + 4] = *(const float4*)(Bp + 4);
        __syncthreads();

        #pragma unroll
        for (int kk = 0; kk < 16; kk++) {
            float a[8], b[8];
            *(float4*)(a)     = *(float4*)&As[kk][ty*8];
            *(float4*)(a + 4) = *(float4*)&As[kk][ty*8 + 4];
            *(float4*)(b)     = *(float4*)&Bs[kk][tx*8];
            *(float4*)(b + 4) = *(float4*)&Bs[kk][tx*8 + 4];
            #pragma unroll
            for (int i = 0; i < 8; i++)
                #pragma unroll
                for (int j = 0; j < 8; j++)
                    acc[i][j] = fmaf(a[i], b[j], acc[i][j]);
        }
        __syncthreads();
    }

    #pragma unroll
    for (int i = 0; i < 8; i++) {
        int row = bm + ty*8 + i;
        float* Cp = C + (size_t)row * N + bn + tx*8;
        float o[8];
        #pragma unroll
        for (int j = 0; j < 8; j++)
            o[j] = acc[i][j] + bias[bn + tx*8 + j];
        *(float4*)(Cp)     = *(float4*)(o);
        *(float4*)(Cp + 4) = *(float4*)(o + 4);
    }
}

// ---------------- 4) FUSED: scores + online softmax + sparse PV + TILE SKIP --------
// R13 semantics, retiled for LDS amortization: 128x128 tile, 256 threads, 8x8
// microtile (half the LDS bytes per FMA), 2 CTAs/SM. Scan: 2 threads/row x 32
// dims. Per-row scan order and ops identical to R13 -> bit-exact result.
#define SCS 132
#define SM_B    16384
#define SM_SC   32768
#define SM_RMX  (SM_SC + 128*SCS*4)       // [128] per-row tile max
#define SM_MROW (SM_RMX + 512)            // [128] per-row running m
#define SMEM_FUSED (SM_MROW + 512)        // 101376 bytes

__global__ __launch_bounds__(256, 2)
void fused_attn_kernel() {
    extern __shared__ __align__(128) char sm[];
    float* As  = (float*)(sm);            // [32][128]  As[k][row]
    float* Bs  = (float*)(sm + SM_B);     // [32][128]  Bs[k][col]
    float* SC  = (float*)(sm + SM_SC);    // [128][SCS]
    float* RMX = (float*)(sm + SM_RMX);   // [128]
    float* MRW = (float*)(sm + SM_MROW);  // [128]

    int tid = threadIdx.x;
    int stile = blockIdx.x, bh = blockIdx.y;
    int b = bh >> 4, h = bh & 15;
    int s0 = stile * 128;
    int tx = tid & 15, ty = tid >> 4;     // ty 0..15: rows ty*8..+7

    const float* X = g_X + ((size_t)bh*2048 + s0)*32;
    const float* Y = g_Y + (size_t)bh*2048*32;

    const float NEG_INF = __int_as_float(0xff800000);
    if (tid < 128) MRW[tid] = NEG_INF;

    // ---- stage A (transposed) once: arow = tid>>1 (0..127), ahalf = tid&1 ----
    {
        int arow = tid >> 1, ahalf = tid & 1;
        const float4* xr = (const float4*)(X + arow*32 + ahalf*16);
        float4 v0 = xr[0], v1 = xr[1], v2 = xr[2], v3 = xr[3];
        int k0 = ahalf*16;
        As[(k0+ 0)*128+arow]=v0.x; As[(k0+ 1)*128+arow]=v0.y;
        As[(k0+ 2)*128+arow]=v0.z; As[(k0+ 3)*128+arow]=v0.w;
        As[(k0+ 4)*128+arow]=v1.x; As[(k0+ 5)*128+arow]=v1.y;
        As[(k0+ 6)*128+arow]=v1.z; As[(k0+ 7)*128+arow]=v1.w;
        As[(k0+ 8)*128+arow]=v2.x; As[(k0+ 9)*128+arow]=v2.y;
        As[(k0+10)*128+arow]=v2.z; As[(k0+11)*128+arow]=v2.w;
        As[(k0+12)*128+arow]=v3.x; As[(k0+13)*128+arow]=v3.y;
        As[(k0+14)*128+arow]=v3.z; As[(k0+15)*128+arow]=v3.w;
    }

    // ---- scan/PV state: row rt = tid>>1 (0..127), half = tid&1 (32 dims each) ----
    int rt = tid >> 1, half = tid & 1;
    const float* vbase = g_vp + (size_t)b*2048*D_ + h*64 + half*32;
    float m   = NEG_INF;
    float den = 0.f;
    float4 o4[8];
    #pragma unroll
    for (int jj = 0; jj < 8; jj++) o4[jj] = make_float4(0.f, 0.f, 0.f, 0.f);

    int brow = tid >> 1, bhalf = tid & 1;

    for (int tt = 0; tt < 16; tt++) {
        int t0 = tt * 128;
        // stage B tile (transposed)
        {
            const float4* yr = (const float4*)(Y + (size_t)(t0 + brow)*32 + bhalf*16);
            float4 v0 = yr[0], v1 = yr[1], v2 = yr[2], v3 = yr[3];
            int k0 = bhalf*16;
            Bs[(k0+ 0)*128+brow]=v0.x; Bs[(k0+ 1)*128+brow]=v0.y;
            Bs[(k0+ 2)*128+brow]=v0.z; Bs[(k0+ 3)*128+brow]=v0.w;
            Bs[(k0+ 4)*128+brow]=v1.x; Bs[(k0+ 5)*128+brow]=v1.y;
            Bs[(k0+ 6)*128+brow]=v1.z; Bs[(k0+ 7)*128+brow]=v1.w;
            Bs[(k0+ 8)*128+brow]=v2.x; Bs[(k0+ 9)*128+brow]=v2.y;
            Bs[(k0+10)*128+brow]=v2.z; Bs[(k0+11)*128+brow]=v2.w;
            Bs[(k0+12)*128+brow]=v3.x; Bs[(k0+13)*128+brow]=v3.y;
            Bs[(k0+14)*128+brow]=v3.z; Bs[(k0+15)*128+brow]=v3.w;
        }
        __syncthreads();

        // ---- 128x128 GEMM tile, 8x8 microtile ----
        float acc[8][8];
        #pragma unroll
        for (int i = 0; i < 8; i++)
            #pragma unroll
            for (int j = 0; j < 8; j++) acc[i][j] = 0.f;

        #pragma unroll
        for (int kk = 0; kk < 32; kk++) {
            float a[8], bb[8];
            *(float4*)(a)      = *(float4*)&As[kk*128 + ty*8];
            *(float4*)(a + 4)  = *(float4*)&As[kk*128 + ty*8 + 4];
            *(float4*)(bb)     = *(float4*)&Bs[kk*128 + tx*8];
            *(float4*)(bb + 4) = *(float4*)&Bs[kk*128 + tx*8 + 4];
            #pragma unroll
            for (int i = 0; i < 8; i++)
                #pragma unroll
                for (int j = 0; j < 8; j++)
                    acc[i][j] = fmaf(a[i], bb[j], acc[i][j]);
        }

        // ---- per-row tile max: butterfly over the 16 tx lanes ----
        float rmx[8];
        #pragma unroll
        for (int i = 0; i < 8; i++) {
            float v = acc[i][0];
            #pragma unroll
            for (int j = 1; j < 8; j++) v = fmaxf(v, acc[i][j]);
            rmx[i] = v;
        }
        #pragma unroll
        for (int msk = 1; msk < 16; msk <<= 1)
            #pragma unroll
            for (int i = 0; i < 8; i++)
                rmx[i] = fmaxf(rmx[i], __shfl_xor_sync(0xFFFFFFFFu, rmx[i], msk));
        if (tx == 0) {
            #pragma unroll
            for (int i = 0; i < 8; i++) RMX[ty*8 + i] = rmx[i];
        }

        // ---- spill only rows that will be scanned ----
        #pragma unroll
        for (int i = 0; i < 8; i++) {
            if (rmx[i] > MRW[ty*8 + i] - 95.0f) {
                *(float4*)&SC[(ty*8+i)*SCS + tx*8]     = *(float4*)&acc[i][0];
                *(float4*)&SC[(ty*8+i)*SCS + tx*8 + 4] = *(float4*)&acc[i][4];
            }
        }
        __syncthreads();

        // ---- scan (tile-row skip, then quad short-circuit) ----
        if (RMX[rt] > m - 95.0f) {
            const float* rp = SC + rt*SCS;
            #pragma unroll 4
            for (int j4 = 0; j4 < 32; j4++) {
                float4 x4 = *(const float4*)(rp + j4*4);
                float mx4 = fmaxf(fmaxf(x4.x, x4.y), fmaxf(x4.z, x4.w));
                if (mx4 <= m - 95.0f) continue;   // whole quad inert (bit-exact)
                float xs[4] = {x4.x, x4.y, x4.z, x4.w};
                #pragma unroll
                for (int u = 0; u < 4; u++) {
                    float x = xs[u];
                    int t = t0 + j4*4 + u;
                    if (x > m) {
                        float r = __expf(m - x);
                        den = den * r + 1.f;
                        const float4* vr = (const float4*)(vbase + (size_t)t * D_);
                        #pragma unroll
                        for (int jj = 0; jj < 8; jj++) {
                            float4 v = vr[jj];
                            o4[jj].x = fmaf(o4[jj].x, r, v.x);
                            o4[jj].y = fmaf(o4[jj].y, r, v.y);
                            o4[jj].z = fmaf(o4[jj].z, r, v.z);
                            o4[jj].w = fmaf(o4[jj].w, r, v.w);
                        }
                        m = x;
                    } else {
                        float dx = x - m;
                        if (dx > -95.0f) {
                            float w = __expf(dx);
                            den += w;
                            const float4* vr = (const float4*)(vbase + (size_t)t * D_);
                            #pragma unroll
                            for (int jj = 0; jj < 8; jj++) {
                                float4 v = vr[jj];
                                o4[jj].x = fmaf(w, v.x, o4[jj].x);
                                o4[jj].y = fmaf(w, v.y, o4[jj].y);
                                o4[jj].z = fmaf(w, v.z, o4[jj].z);
                                o4[jj].w = fmaf(w, v.w, o4[jj].w);
                            }
                        }
                    }
                }
            }
            if (half == 0) MRW[rt] = m;   // mirror running max for next tile's skip
        }
        __syncthreads();   // scan + MRW update done before next spill / B restage
    }

    // ---- write out: o/den -> concat[b, s0+rt, h*64 + half*32 ..] ----
    float inv = 1.f / den;
    float* op = g_concat + ((size_t)(b*2048 + s0 + rt))*D_ + h*64 + half*32;
    #pragma unroll
    for (int jj = 0; jj < 8; jj++) {
        float4 r = o4[jj];
        r.x *= inv; r.y *= inv; r.z *= inv; r.w *= inv;
        *(float4*)(op + jj*4) = r;
    }
}

// ---------------- launcher ----------------
extern "C" void kernel_launch(void* const* d_in, const int* in_sizes, int n_in,
                              void* d_out, int out_size) {
    const float* q    = (const float*)d_in[0];
    // d_in[1] = k (unused in reference forward)
    const float* v    = (const float*)d_in[2];
    const float* Wv   = (const float*)d_in[3];
    const float* bv   = (const float*)d_in[4];
    const float* W_A  = (const float*)d_in[5];
    const float* W_A2 = (const float*)d_in[6];
    const float* Wo   = (const float*)d_in[7];
    const float* bo   = (const float*)d_in[8];
    float* out = (float*)d_out;

    float* vp;     cudaGetSymbolAddress((void**)&vp,     g_vp);
    float* concat; cudaGetSymbolAddress((void**)&concat, g_concat);

    cudaFuncSetAttribute(fused_attn_kernel,
                         cudaFuncAttributeMaxDynamicSharedMemorySize, SMEM_FUSED);

    compute_L_kernel<<<H_, 256>>>(W_A, W_A2);
    xy_kernel<<<B_*S_, 512>>>(q);
    sgemm_nn_bias<<<dim3(D_/128, (B_*S_)/128), 256>>>(B_*S_, D_, D_, v, Wv, bv, vp);
    fused_attn_kernel<<<dim3(S_/128, BH_), 256, SMEM_FUSED>>>();
    sgemm_nn_bias<<<dim3(D_/128, (B_*S_)/128), 256>>>(B_*S_, D_, D_, concat, Wo, bo, out);
}

// round 15
// speedup vs baseline: 3.1824x; 1.3096x over previous
#include <cuda_runtime.h>
#include <cuda_bf16.h>
#include <math.h>
#include <stddef.h>
#include <stdint.h>

// Problem constants
#define B_  2
#define S_  2048
#define D_  1024
#define H_  16
#define FK_ 32
#define DK_ 64
#define BH_ (B_*H_)
#define M_ROWS (B_*S_)      // 4096

// ---------------- scratch (__device__ globals; no allocation allowed) ----------------
__device__ float g_L [H_*DK_*FK_];
__device__ float g_RT[H_*DK_*FK_];
__device__ float g_vp[B_*S_*D_];
__device__ float g_concat[B_*S_*D_];
__device__ float g_X[BH_*S_*FK_];
__device__ float g_Y[BH_*S_*FK_];
// split-bf16 operands for HMMA sgemms
__device__ __nv_bfloat16 g_Ah[M_ROWS*D_], g_Al[M_ROWS*D_];       // activation splits
__device__ __nv_bfloat16 g_WvhT[D_*D_], g_WvlT[D_*D_];           // Wv^T splits [n][k]
__device__ __nv_bfloat16 g_WohT[D_*D_], g_WolT[D_*D_];           // Wo^T splits [n][k]

// ---------------- HMMA helpers (sm_80-era PTX; validated in R7) ----------------
__device__ __forceinline__ uint32_t smem_u32(const void* p) {
    uint32_t a;
    asm("{ .reg .u64 t; cvta.to.shared.u64 t, %1; cvt.u32.u64 %0, t; }" : "=r"(a) : "l"(p));
    return a;
}
__device__ __forceinline__ void ldmx4(uint32_t* r, uint32_t addr) {
    asm volatile("ldmatrix.sync.aligned.m8n8.x4.shared.b16 {%0,%1,%2,%3}, [%4];"
                 : "=r"(r[0]), "=r"(r[1]), "=r"(r[2]), "=r"(r[3]) : "r"(addr));
}
__device__ __forceinline__ void ldmx2(uint32_t* r, uint32_t addr) {
    asm volatile("ldmatrix.sync.aligned.m8n8.x2.shared.b16 {%0,%1}, [%2];"
                 : "=r"(r[0]), "=r"(r[1]) : "r"(addr));
}
__device__ __forceinline__ void mma_bf16(float* c, const uint32_t* a, const uint32_t* b) {
    asm volatile(
        "mma.sync.aligned.m16n8k16.row.col.f32.bf16.bf16.f32 "
        "{%0,%1,%2,%3}, {%4,%5,%6,%7}, {%8,%9}, {%0,%1,%2,%3};"
        : "+f"(c[0]), "+f"(c[1]), "+f"(c[2]), "+f"(c[3])
        : "r"(a[0]), "r"(a[1]), "r"(a[2]), "r"(a[3]), "r"(b[0]), "r"(b[1]));
}
// swizzled offset within a [rows x 64bf16(=128B)] tile
__device__ __forceinline__ uint32_t swoff(int row, int chunk) {
    return (uint32_t)(row * 128 + ((chunk ^ (row & 7)) * 16));
}

// ---------------- 1) collapse Wa@Wb@Wa2 per head (fp32) + RT transpose ----------
__global__ void compute_L_kernel(const float* __restrict__ W_A,
                                 const float* __restrict__ W_A2) {
    int h = blockIdx.x;
    __shared__ float T1[64*64];
    const float* WAh  = W_A  + h*2048;
    const float* WA2h = W_A2 + h*2048;

    for (int idx = threadIdx.x; idx < 4096; idx += blockDim.x) {
        int c = idx >> 6, d = idx & 63;
        float acc = 0.f;
        #pragma unroll 8
        for (int j = 0; j < 32; j++)
            acc = fmaf(WAh[c*32 + j], WAh[j*64 + d], acc);
        T1[idx] = acc;
    }
    __syncthreads();
    for (int idx = threadIdx.x; idx < 2048; idx += blockDim.x) {
        int c = idx >> 5, j = idx & 31;
        float acc = 0.f;
        #pragma unroll 8
        for (int d = 0; d < 64; d++)
            acc = fmaf(T1[c*64 + d], WA2h[d*32 + j], acc);
        g_L[h*2048 + c*32 + j] = acc;
    }
    for (int idx = threadIdx.x; idx < 2048; idx += blockDim.x) {
        int d = idx >> 5, j = idx & 31;
        g_RT[h*2048 + d*32 + j] = WA2h[j*64 + d];
    }
}

// ---------------- 2) X = q.L, Y = q.R^T per head ----------
__global__ __launch_bounds__(512)
void xy_kernel(const float* __restrict__ q) {
    int token = blockIdx.x;
    int b = token >> 11, s = token & 2047;
    __shared__ float qs[D_];
    const float* qrow = q + (size_t)token * D_;
    for (int i = threadIdx.x; i < D_; i += 512) qs[i] = qrow[i];
    __syncthreads();
    int j = threadIdx.x & 31;
    int h = threadIdx.x >> 5;
    const float* qh = qs + h*64;
    const float* Lh  = g_L  + h*2048 + j;
    const float* RTh = g_RT + h*2048 + j;
    float x = 0.f, y = 0.f;
    #pragma unroll 8
    for (int c = 0; c < 64; c++) x = fmaf(qh[c], Lh[c*32], x);
    #pragma unroll 8
    for (int d = 0; d < 64; d++) y = fmaf(qh[d], RTh[d*32], y);
    size_t o = (((size_t)(b*16 + h))*2048 + s)*32 + j;
    g_X[o] = x;
    g_Y[o] = y;
}

// ---------------- 2b) split fp32 -> bf16 hi/lo (row-major, same layout) ----------
__global__ void split_act_kernel(const float* __restrict__ src,
                                 __nv_bfloat16* __restrict__ hi,
                                 __nv_bfloat16* __restrict__ lo) {
    size_t i = (size_t)blockIdx.x * 256 + threadIdx.x;
    float x = src[i];
    __nv_bfloat16 xh = __float2bfloat16(x);
    hi[i] = xh;
    lo[i] = __float2bfloat16(x - __bfloat162float(xh));
}

// ---------------- 2c) split + transpose weights: WT[n][k] = W[k][n] ----------
__global__ void split_wt_kernel(const float* __restrict__ W,
                                __nv_bfloat16* __restrict__ hiT,
                                __nv_bfloat16* __restrict__ loT) {
    int n = blockIdx.x;
    for (int k = threadIdx.x; k < D_; k += 256) {
        float x = W[(size_t)k * D_ + n];
        __nv_bfloat16 xh = __float2bfloat16(x);
        hiT[(size_t)n * D_ + k] = xh;
        loT[(size_t)n * D_ + k] = __float2bfloat16(x - __bfloat162float(xh));
    }
}

// ---------------- 3) split-bf16 HMMA SGEMM: C = A @ W + bias ----------------
// A: [M_ROWS x 1024] via (Ah, Al); W via transposed splits WT[n][k].
// 128x128 tile, K-step 64, 8 warps (4m x 2n), 3-product split accumulation.
#define HS_A  0
#define HS_AL 16384
#define HS_W  32768
#define HS_WL 49152
#define SMEM_HMMA 65536

__global__ __launch_bounds__(256, 2)
void hmma_sgemm(const __nv_bfloat16* __restrict__ Ah,
                const __nv_bfloat16* __restrict__ Al,
                const __nv_bfloat16* __restrict__ WTh,
                const __nv_bfloat16* __restrict__ WTl,
                const float* __restrict__ bias,
                float* __restrict__ C) {
    extern __shared__ __align__(128) char sm[];
    uint32_t smb = smem_u32(sm);

    int tid = threadIdx.x, lane = tid & 31, wid = tid >> 5;
    int bn = blockIdx.x * 128;
    int bm = blockIdx.y * 128;
    int warp_m = wid >> 1;            // 0..3 -> 32 rows
    int warp_n = wid & 1;             // 0..1 -> 64 cols
    int mrow0 = warp_m * 32;
    int nrow0 = warp_n * 64;

    float acc[2][8][4];
    #pragma unroll
    for (int mf = 0; mf < 2; mf++)
        #pragma unroll
        for (int nf = 0; nf < 8; nf++)
            #pragma unroll
            for (int c = 0; c < 4; c++) acc[mf][nf][c] = 0.f;

    int srow = tid >> 1;              // 0..127
    int schk = (tid & 1) * 4;         // chunks 0-3 or 4-7

    for (int kt = 0; kt < 16; kt++) {
        int k0 = kt * 64;
        // stage A hi/lo and WT hi/lo tiles (each 128 rows x 64 bf16, swizzled)
        {
            const uint4* pAh = (const uint4*)(Ah + (size_t)(bm + srow)*D_ + k0);
            const uint4* pAl = (const uint4*)(Al + (size_t)(bm + srow)*D_ + k0);
            const uint4* pWh = (const uint4*)(WTh + (size_t)(bn + srow)*D_ + k0);
            const uint4* pWl = (const uint4*)(WTl + (size_t)(bn + srow)*D_ + k0);
            #pragma unroll
            for (int cc = 0; cc < 4; cc++) {
                uint32_t o = swoff(srow, schk + cc);
                *(uint4*)(sm + HS_A  + o) = pAh[schk + cc];
                *(uint4*)(sm + HS_AL + o) = pAl[schk + cc];
                *(uint4*)(sm + HS_W  + o) = pWh[schk + cc];
                *(uint4*)(sm + HS_WL + o) = pWl[schk + cc];
            }
        }
        __syncthreads();

        #pragma unroll
        for (int ks = 0; ks < 4; ks++) {
            // A fragments (hi, lo) for 2 m-frags
            uint32_t ah[2][4], al[2][4];
            #pragma unroll
            for (int mf = 0; mf < 2; mf++) {
                int row = mrow0 + mf*16 + (lane & 7) + ((lane >> 3) & 1) * 8;
                int chunk = 2*ks + (lane >> 4);
                uint32_t o = swoff(row, chunk);
                ldmx4(ah[mf], smb + HS_A  + o);
                ldmx4(al[mf], smb + HS_AL + o);
            }
            #pragma unroll
            for (int nf = 0; nf < 8; nf++) {
                int row = nrow0 + nf*8 + (lane & 7);
                int chunk = 2*ks + ((lane >> 3) & 1);
                uint32_t o = swoff(row, chunk);
                uint32_t bh[2], bl[2];
                ldmx2(bh, smb + HS_W  + o);
                ldmx2(bl, smb + HS_WL + o);
                #pragma unroll
                for (int mf = 0; mf < 2; mf++) {
                    mma_bf16(acc[mf][nf], ah[mf], bh);
                    mma_bf16(acc[mf][nf], ah[mf], bl);
                    mma_bf16(acc[mf][nf], al[mf], bh);
                }
            }
        }
        __syncthreads();
    }

    // epilogue: c-frag layout -> C + bias
    #pragma unroll
    for (int mf = 0; mf < 2; mf++) {
        int r0 = bm + mrow0 + mf*16 + (lane >> 2);
        #pragma unroll
        for (int nf = 0; nf < 8; nf++) {
            int cc = bn + nrow0 + nf*8 + 2*(lane & 3);
            float2 b01 = make_float2(bias[cc], bias[cc+1]);
            *(float2*)&C[(size_t)r0*D_ + cc] =
                make_float2(acc[mf][nf][0] + b01.x, acc[mf][nf][1] + b01.y);
            *(float2*)&C[(size_t)(r0+8)*D_ + cc] =
                make_float2(acc[mf][nf][2] + b01.x, acc[mf][nf][3] + b01.y);
        }
    }
}

// ---------------- 4) FUSED: identical to R14 (measured 305us, bit-exact) ----------
#define SCS 132
#define SM_B    16384
#define SM_SC   32768
#define SM_RMX  (SM_SC + 128*SCS*4)
#define SM_MROW (SM_RMX + 512)
#define SMEM_FUSED (SM_MROW + 512)

__global__ __launch_bounds__(256, 2)
void fused_attn_kernel() {
    extern __shared__ __align__(128) char sm[];
    float* As  = (float*)(sm);
    float* Bs  = (float*)(sm + SM_B);
    float* SC  = (float*)(sm + SM_SC);
    float* RMX = (float*)(sm + SM_RMX);
    float* MRW = (float*)(sm + SM_MROW);

    int tid = threadIdx.x;
    int stile = blockIdx.x, bh = blockIdx.y;
    int b = bh >> 4, h = bh & 15;
    int s0 = stile * 128;
    int tx = tid & 15, ty = tid >> 4;

    const float* X = g_X + ((size_t)bh*2048 + s0)*32;
    const float* Y = g_Y + (size_t)bh*2048*32;

    const float NEG_INF = __int_as_float(0xff800000);
    if (tid < 128) MRW[tid] = NEG_INF;

    {
        int arow = tid >> 1, ahalf = tid & 1;
        const float4* xr = (const float4*)(X + arow*32 + ahalf*16);
        float4 v0 = xr[0], v1 = xr[1], v2 = xr[2], v3 = xr[3];
        int k0 = ahalf*16;
        As[(k0+ 0)*128+arow]=v0.x; As[(k0+ 1)*128+arow]=v0.y;
        As[(k0+ 2)*128+arow]=v0.z; As[(k0+ 3)*128+arow]=v0.w;
        As[(k0+ 4)*128+arow]=v1.x; As[(k0+ 5)*128+arow]=v1.y;
        As[(k0+ 6)*128+arow]=v1.z; As[(k0+ 7)*128+arow]=v1.w;
        As[(k0+ 8)*128+arow]=v2.x; As[(k0+ 9)*128+arow]=v2.y;
        As[(k0+10)*128+arow]=v2.z; As[(k0+11)*128+arow]=v2.w;
        As[(k0+12)*128+arow]=v3.x; As[(k0+13)*128+arow]=v3.y;
        As[(k0+14)*128+arow]=v3.z; As[(k0+15)*128+arow]=v3.w;
    }

    int rt = tid >> 1, half = tid & 1;
    const float* vbase = g_vp + (size_t)b*2048*D_ + h*64 + half*32;
    float m   = NEG_INF;
    float den = 0.f;
    float4 o4[8];
    #pragma unroll
    for (int jj = 0; jj < 8; jj++) o4[jj] = make_float4(0.f, 0.f, 0.f, 0.f);

    int brow = tid >> 1, bhalf = tid & 1;

    for (int tt = 0; tt < 16; tt++) {
        int t0 = tt * 128;
        {
            const float4* yr = (const float4*)(Y + (size_t)(t0 + brow)*32 + bhalf*16);
            float4 v0 = yr[0], v1 = yr[1], v2 = yr[2], v3 = yr[3];
            int k0 = bhalf*16;
            Bs[(k0+ 0)*128+brow]=v0.x; Bs[(k0+ 1)*128+brow]=v0.y;
            Bs[(k0+ 2)*128+brow]=v0.z; Bs[(k0+ 3)*128+brow]=v0.w;
            Bs[(k0+ 4)*128+brow]=v1.x; Bs[(k0+ 5)*128+brow]=v1.y;
            Bs[(k0+ 6)*128+brow]=v1.z; Bs[(k0+ 7)*128+brow]=v1.w;
            Bs[(k0+ 8)*128+brow]=v2.x; Bs[(k0+ 9)*128+brow]=v2.y;
            Bs[(k0+10)*128+brow]=v2.z; Bs[(k0+11)*128+brow]=v2.w;
            Bs[(k0+12)*128+brow]=v3.x; Bs[(k0+13)*128+brow]=v3.y;
            Bs[(k0+14)*128+brow]=v3.z; Bs[(k0+15)*128+brow]=v3.w;
        }
        __syncthreads();

        float acc[8][8];
        #pragma unroll
        for (int i = 0; i < 8; i++)
            #pragma unroll
            for (int j = 0; j < 8; j++) acc[i][j] = 0.f;

        #pragma unroll
        for (int kk = 0; kk < 32; kk++) {
            float a[8], bb[8];
            *(float4*)(a)      = *(float4*)&As[kk*128 + ty*8];
            *(float4*)(a + 4)  = *(float4*)&As[kk*128 + ty*8 + 4];
            *(float4*)(bb)     = *(float4*)&Bs[kk*128 + tx*8];
            *(float4*)(bb + 4) = *(float4*)&Bs[kk*128 + tx*8 + 4];
            #pragma unroll
            for (int i = 0; i < 8; i++)
                #pragma unroll
                for (int j = 0; j < 8; j++)
                    acc[i][j] = fmaf(a[i], bb[j], acc[i][j]);
        }

        float rmx[8];
        #pragma unroll
        for (int i = 0; i < 8; i++) {
            float v = acc[i][0];
            #pragma unroll
            for (int j = 1; j < 8; j++) v = fmaxf(v, acc[i][j]);
            rmx[i] = v;
        }
        #pragma unroll
        for (int msk = 1; msk < 16; msk <<= 1)
            #pragma unroll
            for (int i = 0; i < 8; i++)
                rmx[i] = fmaxf(rmx[i], __shfl_xor_sync(0xFFFFFFFFu, rmx[i], msk));
        if (tx == 0) {
            #pragma unroll
            for (int i = 0; i < 8; i++) RMX[ty*8 + i] = rmx[i];
        }

        #pragma unroll
        for (int i = 0; i < 8; i++) {
            if (rmx[i] > MRW[ty*8 + i] - 95.0f) {
                *(float4*)&SC[(ty*8+i)*SCS + tx*8]     = *(float4*)&acc[i][0];
                *(float4*)&SC[(ty*8+i)*SCS + tx*8 + 4] = *(float4*)&acc[i][4];
            }
        }
        __syncthreads();

        if (RMX[rt] > m - 95.0f) {
            const float* rp = SC + rt*SCS;
            #pragma unroll 4
            for (int j4 = 0; j4 < 32; j4++) {
                float4 x4 = *(const float4*)(rp + j4*4);
                float mx4 = fmaxf(fmaxf(x4.x, x4.y), fmaxf(x4.z, x4.w));
                if (mx4 <= m - 95.0f) continue;
                float xs[4] = {x4.x, x4.y, x4.z, x4.w};
                #pragma unroll
                for (int u = 0; u < 4; u++) {
                    float x = xs[u];
                    int t = t0 + j4*4 + u;
                    if (x > m) {
                        float r = __expf(m - x);
                        den = den * r + 1.f;
                        const float4* vr = (const float4*)(vbase + (size_t)t * D_);
                        #pragma unroll
                        for (int jj = 0; jj < 8; jj++) {
                            float4 v = vr[jj];
                            o4[jj].x = fmaf(o4[jj].x, r, v.x);
                            o4[jj].y = fmaf(o4[jj].y, r, v.y);
                            o4[jj].z = fmaf(o4[jj].z, r, v.z);
                            o4[jj].w = fmaf(o4[jj].w, r, v.w);
                        }
                        m = x;
                    } else {
                        float dx = x - m;
                        if (dx > -95.0f) {
                            float w = __expf(dx);
                            den += w;
                            const float4* vr = (const float4*)(vbase + (size_t)t * D_);
                            #pragma unroll
                            for (int jj = 0; jj < 8; jj++) {
                                float4 v = vr[jj];
                                o4[jj].x = fmaf(w, v.x, o4[jj].x);
                                o4[jj].y = fmaf(w, v.y, o4[jj].y);
                                o4[jj].z = fmaf(w, v.z, o4[jj].z);
                                o4[jj].w = fmaf(w, v.w, o4[jj].w);
                            }
                        }
                    }
                }
            }
            if (half == 0) MRW[rt] = m;
        }
        __syncthreads();
    }

    float inv = 1.f / den;
    float* op = g_concat + ((size_t)(b*2048 + s0 + rt))*D_ + h*64 + half*32;
    #pragma unroll
    for (int jj = 0; jj < 8; jj++) {
        float4 r = o4[jj];
        r.x *= inv; r.y *= inv; r.z *= inv; r.w *= inv;
        *(float4*)(op + jj*4) = r;
    }
}

// ---------------- launcher ----------------
extern "C" void kernel_launch(void* const* d_in, const int* in_sizes, int n_in,
                              void* d_out, int out_size) {
    const float* q    = (const float*)d_in[0];
    // d_in[1] = k (unused in reference forward)
    const float* v    = (const float*)d_in[2];
    const float* Wv   = (const float*)d_in[3];
    const float* bv   = (const float*)d_in[4];
    const float* W_A  = (const float*)d_in[5];
    const float* W_A2 = (const float*)d_in[6];
    const float* Wo   = (const float*)d_in[7];
    const float* bo   = (const float*)d_in[8];
    float* out = (float*)d_out;

    float* vp;     cudaGetSymbolAddress((void**)&vp,     g_vp);
    float* concat; cudaGetSymbolAddress((void**)&concat, g_concat);
    __nv_bfloat16 *Ah, *Al, *WvhT, *WvlT, *WohT, *WolT;
    cudaGetSymbolAddress((void**)&Ah,   g_Ah);
    cudaGetSymbolAddress((void**)&Al,   g_Al);
    cudaGetSymbolAddress((void**)&WvhT, g_WvhT);
    cudaGetSymbolAddress((void**)&WvlT, g_WvlT);
    cudaGetSymbolAddress((void**)&WohT, g_WohT);
    cudaGetSymbolAddress((void**)&WolT, g_WolT);

    cudaFuncSetAttribute(fused_attn_kernel,
                         cudaFuncAttributeMaxDynamicSharedMemorySize, SMEM_FUSED);
    cudaFuncSetAttribute(hmma_sgemm,
                         cudaFuncAttributeMaxDynamicSharedMemorySize, SMEM_HMMA);

    compute_L_kernel<<<H_, 256>>>(W_A, W_A2);
    xy_kernel<<<B_*S_, 512>>>(q);
    // sgemm #1: vp = v @ Wv + bv  (split-bf16 HMMA)
    split_wt_kernel<<<D_, 256>>>(Wv, WvhT, WvlT);
    split_act_kernel<<<(M_ROWS*D_)/256, 256>>>(v, Ah, Al);
    hmma_sgemm<<<dim3(D_/128, M_ROWS/128), 256, SMEM_HMMA>>>(Ah, Al, WvhT, WvlT, bv, vp);
    // attention
    fused_attn_kernel<<<dim3(S_/128, BH_), 256, SMEM_FUSED>>>();
    // sgemm #2: out = concat @ Wo + bo  (split-bf16 HMMA)
    split_wt_kernel<<<D_, 256>>>(Wo, WohT, WolT);
    split_act_kernel<<<(M_ROWS*D_)/256, 256>>>(concat, Ah, Al);
    hmma_sgemm<<<dim3(D_/128, M_ROWS/128), 256, SMEM_HMMA>>>(Ah, Al, WohT, WolT, bo, out);
}

// round 16
// speedup vs baseline: 3.2459x; 1.0200x over previous
#include <cuda_runtime.h>
#include <cuda_bf16.h>
#include <math.h>
#include <stddef.h>
#include <stdint.h>

// Problem constants
#define B_  2
#define S_  2048
#define D_  1024
#define H_  16
#define FK_ 32
#define DK_ 64
#define BH_ (B_*H_)
#define M_ROWS (B_*S_)      // 4096

// ---------------- scratch (__device__ globals; no allocation allowed) ----------------
__device__ float g_L [H_*DK_*FK_];
__device__ float g_RT[H_*DK_*FK_];
__device__ float g_vp[B_*S_*D_];
__device__ float g_concat[B_*S_*D_];
__device__ float g_X[BH_*S_*FK_];
__device__ float g_Y[BH_*S_*FK_];
__device__ __nv_bfloat16 g_WvhT[D_*D_], g_WvlT[D_*D_];           // Wv^T splits [n][k]
__device__ __nv_bfloat16 g_WohT[D_*D_], g_WolT[D_*D_];           // Wo^T splits [n][k]

// ---------------- HMMA helpers ----------------
__device__ __forceinline__ uint32_t smem_u32(const void* p) {
    uint32_t a;
    asm("{ .reg .u64 t; cvta.to.shared.u64 t, %1; cvt.u32.u64 %0, t; }" : "=r"(a) : "l"(p));
    return a;
}
__device__ __forceinline__ void ldmx4(uint32_t* r, uint32_t addr) {
    asm volatile("ldmatrix.sync.aligned.m8n8.x4.shared.b16 {%0,%1,%2,%3}, [%4];"
                 : "=r"(r[0]), "=r"(r[1]), "=r"(r[2]), "=r"(r[3]) : "r"(addr));
}
__device__ __forceinline__ void ldmx2(uint32_t* r, uint32_t addr) {
    asm volatile("ldmatrix.sync.aligned.m8n8.x2.shared.b16 {%0,%1}, [%2];"
                 : "=r"(r[0]), "=r"(r[1]) : "r"(addr));
}
__device__ __forceinline__ void mma_bf16(float* c, const uint32_t* a, const uint32_t* b) {
    asm volatile(
        "mma.sync.aligned.m16n8k16.row.col.f32.bf16.bf16.f32 "
        "{%0,%1,%2,%3}, {%4,%5,%6,%7}, {%8,%9}, {%0,%1,%2,%3};"
        : "+f"(c[0]), "+f"(c[1]), "+f"(c[2]), "+f"(c[3])
        : "r"(a[0]), "r"(a[1]), "r"(a[2]), "r"(a[3]), "r"(b[0]), "r"(b[1]));
}
__device__ __forceinline__ uint32_t swoff(int row, int chunk) {
    return (uint32_t)(row * 128 + ((chunk ^ (row & 7)) * 16));
}
__device__ __forceinline__ uint32_t pack_hi2(float a, float b) {
    __nv_bfloat162 t = __floats2bfloat162_rn(a, b);
    return *(uint32_t*)&t;
}

// ---------------- 1) collapse Wa@Wb@Wa2 per head (fp32) + RT transpose ----------
__global__ void compute_L_kernel(const float* __restrict__ W_A,
                                 const float* __restrict__ W_A2) {
    int h = blockIdx.x;
    __shared__ float T1[64*64];
    const float* WAh  = W_A  + h*2048;
    const float* WA2h = W_A2 + h*2048;

    for (int idx = threadIdx.x; idx < 4096; idx += blockDim.x) {
        int c = idx >> 6, d = idx & 63;
        float acc = 0.f;
        #pragma unroll 8
        for (int j = 0; j < 32; j++)
            acc = fmaf(WAh[c*32 + j], WAh[j*64 + d], acc);
        T1[idx] = acc;
    }
    __syncthreads();
    for (int idx = threadIdx.x; idx < 2048; idx += blockDim.x) {
        int c = idx >> 5, j = idx & 31;
        float acc = 0.f;
        #pragma unroll 8
        for (int d = 0; d < 64; d++)
            acc = fmaf(T1[c*64 + d], WA2h[d*32 + j], acc);
        g_L[h*2048 + c*32 + j] = acc;
    }
    for (int idx = threadIdx.x; idx < 2048; idx += blockDim.x) {
        int d = idx >> 5, j = idx & 31;
        g_RT[h*2048 + d*32 + j] = WA2h[j*64 + d];
    }
}

// ---------------- 2) X = q.L, Y = q.R^T per head ----------
__global__ __launch_bounds__(512)
void xy_kernel(const float* __restrict__ q) {
    int token = blockIdx.x;
    int b = token >> 11, s = token & 2047;
    __shared__ float qs[D_];
    const float* qrow = q + (size_t)token * D_;
    for (int i = threadIdx.x; i < D_; i += 512) qs[i] = qrow[i];
    __syncthreads();
    int j = threadIdx.x & 31;
    int h = threadIdx.x >> 5;
    const float* qh = qs + h*64;
    const float* Lh  = g_L  + h*2048 + j;
    const float* RTh = g_RT + h*2048 + j;
    float x = 0.f, y = 0.f;
    #pragma unroll 8
    for (int c = 0; c < 64; c++) x = fmaf(qh[c], Lh[c*32], x);
    #pragma unroll 8
    for (int d = 0; d < 64; d++) y = fmaf(qh[d], RTh[d*32], y);
    size_t o = (((size_t)(b*16 + h))*2048 + s)*32 + j;
    g_X[o] = x;
    g_Y[o] = y;
}

// ---------------- 2c) split + transpose weights (smem-tiled, coalesced both ways) --
__global__ __launch_bounds__(256)
void split_wt_kernel(const float* __restrict__ W,
                     __nv_bfloat16* __restrict__ hiT,
                     __nv_bfloat16* __restrict__ loT) {
    __shared__ float t[32][33];
    int n0 = blockIdx.x * 32, k0 = blockIdx.y * 32;
    int x = threadIdx.x & 31, y = threadIdx.x >> 5;   // 32x8
    #pragma unroll
    for (int i = y; i < 32; i += 8)
        t[i][x] = W[(size_t)(k0 + i) * D_ + n0 + x];  // t[k_local][n_local]
    __syncthreads();
    #pragma unroll
    for (int i = y; i < 32; i += 8) {
        float v = t[x][i];                            // k_local=x, n_local=i
        __nv_bfloat16 vh = __float2bfloat16(v);
        size_t o = (size_t)(n0 + i) * D_ + k0 + x;    // [n][k], k contiguous
        hiT[o] = vh;
        loT[o] = __float2bfloat16(v - __bfloat162float(vh));
    }
}

// ---------------- 3) split-bf16 HMMA SGEMM with INLINE activation split ----------
// C = A(fp32) @ W + bias. A is split hi/lo during staging (no standalone pass).
#define HS_A  0
#define HS_AL 16384
#define HS_W  32768
#define HS_WL 49152
#define SMEM_HMMA 65536

__global__ __launch_bounds__(256, 2)
void hmma_sgemm(const float* __restrict__ A,
                const __nv_bfloat16* __restrict__ WTh,
                const __nv_bfloat16* __restrict__ WTl,
                const float* __restrict__ bias,
                float* __restrict__ C) {
    extern __shared__ __align__(128) char sm[];
    uint32_t smb = smem_u32(sm);

    int tid = threadIdx.x, lane = tid & 31, wid = tid >> 5;
    int bn = blockIdx.x * 128;
    int bm = blockIdx.y * 128;
    int warp_m = wid >> 1;
    int warp_n = wid & 1;
    int mrow0 = warp_m * 32;
    int nrow0 = warp_n * 64;

    float acc[2][8][4];
    #pragma unroll
    for (int mf = 0; mf < 2; mf++)
        #pragma unroll
        for (int nf = 0; nf < 8; nf++)
            #pragma unroll
            for (int c = 0; c < 4; c++) acc[mf][nf][c] = 0.f;

    int srow = tid >> 1;              // 0..127
    int shalf = tid & 1;              // bf16 chunks 0-3 or 4-7

    for (int kt = 0; kt < 16; kt++) {
        int k0 = kt * 64;
        // stage: A fp32 -> split hi/lo bf16 tiles; W pre-split tiles
        {
            const float4* pA = (const float4*)(A + (size_t)(bm + srow)*D_ + k0);
            const uint4*  pWh = (const uint4*)(WTh + (size_t)(bn + srow)*D_ + k0);
            const uint4*  pWl = (const uint4*)(WTl + (size_t)(bn + srow)*D_ + k0);
            #pragma unroll
            for (int cc = 0; cc < 4; cc++) {
                int chunk = shalf*4 + cc;              // bf16 16B chunk (8 values)
                float4 f0 = pA[chunk*2];
                float4 f1 = pA[chunk*2 + 1];
                __nv_bfloat16 h0 = __float2bfloat16(f0.x), h1 = __float2bfloat16(f0.y);
                __nv_bfloat16 h2 = __float2bfloat16(f0.z), h3 = __float2bfloat16(f0.w);
                __nv_bfloat16 h4 = __float2bfloat16(f1.x), h5 = __float2bfloat16(f1.y);
                __nv_bfloat16 h6 = __float2bfloat16(f1.z), h7 = __float2bfloat16(f1.w);
                uint4 hv, lv;
                hv.x = pack_hi2(f0.x, f0.y); hv.y = pack_hi2(f0.z, f0.w);
                hv.z = pack_hi2(f1.x, f1.y); hv.w = pack_hi2(f1.z, f1.w);
                lv.x = pack_hi2(f0.x - __bfloat162float(h0), f0.y - __bfloat162float(h1));
                lv.y = pack_hi2(f0.z - __bfloat162float(h2), f0.w - __bfloat162float(h3));
                lv.z = pack_hi2(f1.x - __bfloat162float(h4), f1.y - __bfloat162float(h5));
                lv.w = pack_hi2(f1.z - __bfloat162float(h6), f1.w - __bfloat162float(h7));
                uint32_t o = swoff(srow, chunk);
                *(uint4*)(sm + HS_A  + o) = hv;
                *(uint4*)(sm + HS_AL + o) = lv;
                *(uint4*)(sm + HS_W  + o) = pWh[chunk];
                *(uint4*)(sm + HS_WL + o) = pWl[chunk];
            }
        }
        __syncthreads();

        #pragma unroll
        for (int ks = 0; ks < 4; ks++) {
            uint32_t ah[2][4], al[2][4];
            #pragma unroll
            for (int mf = 0; mf < 2; mf++) {
                int row = mrow0 + mf*16 + (lane & 7) + ((lane >> 3) & 1) * 8;
                int chunk = 2*ks + (lane >> 4);
                uint32_t o = swoff(row, chunk);
                ldmx4(ah[mf], smb + HS_A  + o);
                ldmx4(al[mf], smb + HS_AL + o);
            }
            #pragma unroll
            for (int nf = 0; nf < 8; nf++) {
                int row = nrow0 + nf*8 + (lane & 7);
                int chunk = 2*ks + ((lane >> 3) & 1);
                uint32_t o = swoff(row, chunk);
                uint32_t bh[2], bl[2];
                ldmx2(bh, smb + HS_W  + o);
                ldmx2(bl, smb + HS_WL + o);
                #pragma unroll
                for (int mf = 0; mf < 2; mf++) {
                    mma_bf16(acc[mf][nf], ah[mf], bh);
                    mma_bf16(acc[mf][nf], ah[mf], bl);
                    mma_bf16(acc[mf][nf], al[mf], bh);
                }
            }
        }
        __syncthreads();
    }

    #pragma unroll
    for (int mf = 0; mf < 2; mf++) {
        int r0 = bm + mrow0 + mf*16 + (lane >> 2);
        #pragma unroll
        for (int nf = 0; nf < 8; nf++) {
            int cc = bn + nrow0 + nf*8 + 2*(lane & 3);
            float2 b01 = make_float2(bias[cc], bias[cc+1]);
            *(float2*)&C[(size_t)r0*D_ + cc] =
                make_float2(acc[mf][nf][0] + b01.x, acc[mf][nf][1] + b01.y);
            *(float2*)&C[(size_t)(r0+8)*D_ + cc] =
                make_float2(acc[mf][nf][2] + b01.x, acc[mf][nf][3] + b01.y);
        }
    }
}

// ---------------- 4) FUSED: R14 semantics, conflict-free staging remap ----------
#define SCS 132
#define SM_B    16384
#define SM_SC   32768
#define SM_RMX  (SM_SC + 128*SCS*4)
#define SM_MROW (SM_RMX + 512)
#define SMEM_FUSED (SM_MROW + 512)

__global__ __launch_bounds__(256, 2)
void fused_attn_kernel() {
    extern __shared__ __align__(128) char sm[];
    float* As  = (float*)(sm);
    float* Bs  = (float*)(sm + SM_B);
    float* SC  = (float*)(sm + SM_SC);
    float* RMX = (float*)(sm + SM_RMX);
    float* MRW = (float*)(sm + SM_MROW);

    int tid = threadIdx.x;
    int stile = blockIdx.x, bh = blockIdx.y;
    int b = bh >> 4, h = bh & 15;
    int s0 = stile * 128;
    int tx = tid & 15, ty = tid >> 4;

    const float* X = g_X + ((size_t)bh*2048 + s0)*32;
    const float* Y = g_Y + (size_t)bh*2048*32;

    const float NEG_INF = __int_as_float(0xff800000);
    if (tid < 128) MRW[tid] = NEG_INF;

    // staging thread map: 32 consecutive rows per warp -> conflict-free STS
    int srow = tid & 127, shalf = tid >> 7;

    // ---- stage A (transposed) once ----
    {
        const float4* xr = (const float4*)(X + srow*32 + shalf*16);
        float4 v0 = xr[0], v1 = xr[1], v2 = xr[2], v3 = xr[3];
        int k0 = shalf*16;
        As[(k0+ 0)*128+srow]=v0.x; As[(k0+ 1)*128+srow]=v0.y;
        As[(k0+ 2)*128+srow]=v0.z; As[(k0+ 3)*128+srow]=v0.w;
        As[(k0+ 4)*128+srow]=v1.x; As[(k0+ 5)*128+srow]=v1.y;
        As[(k0+ 6)*128+srow]=v1.z; As[(k0+ 7)*128+srow]=v1.w;
        As[(k0+ 8)*128+srow]=v2.x; As[(k0+ 9)*128+srow]=v2.y;
        As[(k0+10)*128+srow]=v2.z; As[(k0+11)*128+srow]=v2.w;
        As[(k0+12)*128+srow]=v3.x; As[(k0+13)*128+srow]=v3.y;
        As[(k0+14)*128+srow]=v3.z; As[(k0+15)*128+srow]=v3.w;
    }

    int rt = tid >> 1, half = tid & 1;
    const float* vbase = g_vp + (size_t)b*2048*D_ + h*64 + half*32;
    float m   = NEG_INF;
    float den = 0.f;
    float4 o4[8];
    #pragma unroll
    for (int jj = 0; jj < 8; jj++) o4[jj] = make_float4(0.f, 0.f, 0.f, 0.f);

    for (int tt = 0; tt < 16; tt++) {
        int t0 = tt * 128;
        // stage B tile (transposed, conflict-free map)
        {
            const float4* yr = (const float4*)(Y + (size_t)(t0 + srow)*32 + shalf*16);
            float4 v0 = yr[0], v1 = yr[1], v2 = yr[2], v3 = yr[3];
            int k0 = shalf*16;
            Bs[(k0+ 0)*128+srow]=v0.x; Bs[(k0+ 1)*128+srow]=v0.y;
            Bs[(k0+ 2)*128+srow]=v0.z; Bs[(k0+ 3)*128+srow]=v0.w;
            Bs[(k0+ 4)*128+srow]=v1.x; Bs[(k0+ 5)*128+srow]=v1.y;
            Bs[(k0+ 6)*128+srow]=v1.z; Bs[(k0+ 7)*128+srow]=v1.w;
            Bs[(k0+ 8)*128+srow]=v2.x; Bs[(k0+ 9)*128+srow]=v2.y;
            Bs[(k0+10)*128+srow]=v2.z; Bs[(k0+11)*128+srow]=v2.w;
            Bs[(k0+12)*128+srow]=v3.x; Bs[(k0+13)*128+srow]=v3.y;
            Bs[(k0+14)*128+srow]=v3.z; Bs[(k0+15)*128+srow]=v3.w;
        }
        __syncthreads();

        float acc[8][8];
        #pragma unroll
        for (int i = 0; i < 8; i++)
            #pragma unroll
            for (int j = 0; j < 8; j++) acc[i][j] = 0.f;

        #pragma unroll
        for (int kk = 0; kk < 32; kk++) {
            float a[8], bb[8];
            *(float4*)(a)      = *(float4*)&As[kk*128 + ty*8];
            *(float4*)(a + 4)  = *(float4*)&As[kk*128 + ty*8 + 4];
            *(float4*)(bb)     = *(float4*)&Bs[kk*128 + tx*8];
            *(float4*)(bb + 4) = *(float4*)&Bs[kk*128 + tx*8 + 4];
            #pragma unroll
            for (int i = 0; i < 8; i++)
                #pragma unroll
                for (int j = 0; j < 8; j++)
                    acc[i][j] = fmaf(a[i], bb[j], acc[i][j]);
        }

        float rmx[8];
        #pragma unroll
        for (int i = 0; i < 8; i++) {
            float v = acc[i][0];
            #pragma unroll
            for (int j = 1; j < 8; j++) v = fmaxf(v, acc[i][j]);
            rmx[i] = v;
        }
        #pragma unroll
        for (int msk = 1; msk < 16; msk <<= 1)
            #pragma unroll
            for (int i = 0; i < 8; i++)
                rmx[i] = fmaxf(rmx[i], __shfl_xor_sync(0xFFFFFFFFu, rmx[i], msk));
        if (tx == 0) {
            #pragma unroll
            for (int i = 0; i < 8; i++) RMX[ty*8 + i] = rmx[i];
        }

        #pragma unroll
        for (int i = 0; i < 8; i++) {
            if (rmx[i] > MRW[ty*8 + i] - 95.0f) {
                *(float4*)&SC[(ty*8+i)*SCS + tx*8]     = *(float4*)&acc[i][0];
                *(float4*)&SC[(ty*8+i)*SCS + tx*8 + 4] = *(float4*)&acc[i][4];
            }
        }
        __syncthreads();

        if (RMX[rt] > m - 95.0f) {
            const float* rp = SC + rt*SCS;
            #pragma unroll 4
            for (int j4 = 0; j4 < 32; j4++) {
                float4 x4 = *(const float4*)(rp + j4*4);
                float mx4 = fmaxf(fmaxf(x4.x, x4.y), fmaxf(x4.z, x4.w));
                if (mx4 <= m - 95.0f) continue;
                float xs[4] = {x4.x, x4.y, x4.z, x4.w};
                #pragma unroll
                for (int u = 0; u < 4; u++) {
                    float x = xs[u];
                    int t = t0 + j4*4 + u;
                    if (x > m) {
                        float r = __expf(m - x);
                        den = den * r + 1.f;
                        const float4* vr = (const float4*)(vbase + (size_t)t * D_);
                        #pragma unroll
                        for (int jj = 0; jj < 8; jj++) {
                            float4 v = vr[jj];
                            o4[jj].x = fmaf(o4[jj].x, r, v.x);
                            o4[jj].y = fmaf(o4[jj].y, r, v.y);
                            o4[jj].z = fmaf(o4[jj].z, r, v.z);
                            o4[jj].w = fmaf(o4[jj].w, r, v.w);
                        }
                        m = x;
                    } else {
                        float dx = x - m;
                        if (dx > -95.0f) {
                            float w = __expf(dx);
                            den += w;
                            const float4* vr = (const float4*)(vbase + (size_t)t * D_);
                            #pragma unroll
                            for (int jj = 0; jj < 8; jj++) {
                                float4 v = vr[jj];
                                o4[jj].x = fmaf(w, v.x, o4[jj].x);
                                o4[jj].y = fmaf(w, v.y, o4[jj].y);
                                o4[jj].z = fmaf(w, v.z, o4[jj].z);
                                o4[jj].w = fmaf(w, v.w, o4[jj].w);
                            }
                        }
                    }
                }
            }
            if (half == 0) MRW[rt] = m;
        }
        __syncthreads();
    }

    float inv = 1.f / den;
    float* op = g_concat + ((size_t)(b*2048 + s0 + rt))*D_ + h*64 + half*32;
    #pragma unroll
    for (int jj = 0; jj < 8; jj++) {
        float4 r = o4[jj];
        r.x *= inv; r.y *= inv; r.z *= inv; r.w *= inv;
        *(float4*)(op + jj*4) = r;
    }
}

// ---------------- launcher ----------------
extern "C" void kernel_launch(void* const* d_in, const int* in_sizes, int n_in,
                              void* d_out, int out_size) {
    const float* q    = (const float*)d_in[0];
    // d_in[1] = k (unused in reference forward)
    const float* v    = (const float*)d_in[2];
    const float* Wv   = (const float*)d_in[3];
    const float* bv   = (const float*)d_in[4];
    const float* W_A  = (const float*)d_in[5];
    const float* W_A2 = (const float*)d_in[6];
    const float* Wo   = (const float*)d_in[7];
    const float* bo   = (const float*)d_in[8];
    float* out = (float*)d_out;

    float* vp;     cudaGetSymbolAddress((void**)&vp,     g_vp);
    float* concat; cudaGetSymbolAddress((void**)&concat, g_concat);
    __nv_bfloat16 *WvhT, *WvlT, *WohT, *WolT;
    cudaGetSymbolAddress((void**)&WvhT, g_WvhT);
    cudaGetSymbolAddress((void**)&WvlT, g_WvlT);
    cudaGetSymbolAddress((void**)&WohT, g_WohT);
    cudaGetSymbolAddress((void**)&WolT, g_WolT);

    cudaFuncSetAttribute(fused_attn_kernel,
                         cudaFuncAttributeMaxDynamicSharedMemorySize, SMEM_FUSED);
    cudaFuncSetAttribute(hmma_sgemm,
                         cudaFuncAttributeMaxDynamicSharedMemorySize, SMEM_HMMA);

    compute_L_kernel<<<H_, 256>>>(W_A, W_A2);
    xy_kernel<<<B_*S_, 512>>>(q);
    split_wt_kernel<<<dim3(32, 32), 256>>>(Wv, WvhT, WvlT);
    split_wt_kernel<<<dim3(32, 32), 256>>>(Wo, WohT, WolT);
    // sgemm #1: vp = v @ Wv + bv  (inline-split HMMA)
    hmma_sgemm<<<dim3(D_/128, M_ROWS/128), 256, SMEM_HMMA>>>(v, WvhT, WvlT, bv, vp);
    // attention
    fused_attn_kernel<<<dim3(S_/128, BH_), 256, SMEM_FUSED>>>();
    // sgemm #2: out = concat @ Wo + bo
    hmma_sgemm<<<dim3(D_/128, M_ROWS/128), 256, SMEM_HMMA>>>(concat, WohT, WolT, bo, out);
}